// round 7
// baseline (speedup 1.0000x reference)
#include <cuda_runtime.h>
#include <cuda_bf16.h>
#include <cstdint>
#include <math.h>

// ---------------------------------------------------------------------------
// BiMamba: bidirectional Mamba block, fp32 throughout.
// B=8, L=2048, D_MODEL=512, D_INNER=1024, D_STATE=16, DT_RANK=32, D_CONV=4
// ---------------------------------------------------------------------------

#define BATCH   8
#define SEQLEN  2048
#define DMODEL  512
#define DINNER  1024
#define DSTATE  16
#define DTRANK  32
#define MT      (BATCH * SEQLEN)          // 16384 token rows

// --------------------------- scratch (device globals) ----------------------
__device__ float g_xz  [2][(size_t)MT * 2048];   // xi | z   (per dir)
__device__ float g_xc  [2][(size_t)MT * 1024];   // conv+silu output
__device__ float g_dbl [2][(size_t)MT * 64];     // dt_lowrank | B | C
__device__ float g_dt  [2][(size_t)MT * 1024];   // softplus dt
__device__ float g_yg  [2][(size_t)MT * 1024];   // gated scan output
__device__ float g_ycat[(size_t)MT * 1024];      // concat(y_fwd, y_bwd)

// --------------------------- helpers ---------------------------------------
__device__ __forceinline__ float softplus_f(float v) {
    return v > 20.f ? v : log1pf(__expf(v));
}

// ---------------------------------------------------------------------------
// NT SGEMM: C[m,n] = sum_k A[m*lda+k] * B[n*ldb+k]  (+ epilogue)
// 128x128 tile, BK=8, 256 threads, 8x8 per thread, double-buffered smem.
// EPI: 0 = none, 1 = softplus(v + bias[n]), 2 = v + bias[n]
// ---------------------------------------------------------------------------
template <int EPI>
__global__ __launch_bounds__(256, 2)
void gemm_nt(const float* __restrict__ A, const float* __restrict__ B,
             float* __restrict__ C, const float* __restrict__ bias,
             int M, int N, int K, int lda, int ldb, int ldc)
{
    __shared__ float As[2][8][128];
    __shared__ float Bs[2][8][128];

    const int tid = threadIdx.x;
    const int bm  = blockIdx.y * 128;
    const int bn  = blockIdx.x * 128;
    const int lr  = tid >> 1;          // 0..127 tile row for loading
    const int kc  = (tid & 1) * 4;     // k sub-offset (0 or 4)
    const int ty  = tid >> 4;          // 0..15
    const int tx  = tid & 15;          // 0..15

    float acc[8][8];
#pragma unroll
    for (int i = 0; i < 8; i++)
#pragma unroll
        for (int j = 0; j < 8; j++) acc[i][j] = 0.f;

    const int KT = K >> 3;
    const float* Ap = A + (size_t)(bm + lr) * lda + kc;
    const float* Bp = B + (size_t)(bn + lr) * ldb + kc;
    const bool aok = (bm + lr) < M;
    const bool bok = (bn + lr) < N;

    float4 av = aok ? __ldg((const float4*)Ap) : make_float4(0.f, 0.f, 0.f, 0.f);
    float4 bv = bok ? __ldg((const float4*)Bp) : make_float4(0.f, 0.f, 0.f, 0.f);
    As[0][kc + 0][lr] = av.x; As[0][kc + 1][lr] = av.y;
    As[0][kc + 2][lr] = av.z; As[0][kc + 3][lr] = av.w;
    Bs[0][kc + 0][lr] = bv.x; Bs[0][kc + 1][lr] = bv.y;
    Bs[0][kc + 2][lr] = bv.z; Bs[0][kc + 3][lr] = bv.w;
    __syncthreads();

    int buf = 0;
    for (int kt = 0; kt < KT; kt++) {
        if (kt + 1 < KT) {
            av = aok ? __ldg((const float4*)(Ap + (kt + 1) * 8))
                     : make_float4(0.f, 0.f, 0.f, 0.f);
            bv = bok ? __ldg((const float4*)(Bp + (kt + 1) * 8))
                     : make_float4(0.f, 0.f, 0.f, 0.f);
        }
#pragma unroll
        for (int k = 0; k < 8; k++) {
            float a[8], b[8];
            *(float4*)&a[0] = *(const float4*)&As[buf][k][ty * 8];
            *(float4*)&a[4] = *(const float4*)&As[buf][k][ty * 8 + 4];
            *(float4*)&b[0] = *(const float4*)&Bs[buf][k][tx * 8];
            *(float4*)&b[4] = *(const float4*)&Bs[buf][k][tx * 8 + 4];
#pragma unroll
            for (int i = 0; i < 8; i++)
#pragma unroll
                for (int j = 0; j < 8; j++)
                    acc[i][j] = fmaf(a[i], b[j], acc[i][j]);
        }
        if (kt + 1 < KT) {
            const int nb = buf ^ 1;
            As[nb][kc + 0][lr] = av.x; As[nb][kc + 1][lr] = av.y;
            As[nb][kc + 2][lr] = av.z; As[nb][kc + 3][lr] = av.w;
            Bs[nb][kc + 0][lr] = bv.x; Bs[nb][kc + 1][lr] = bv.y;
            Bs[nb][kc + 2][lr] = bv.z; Bs[nb][kc + 3][lr] = bv.w;
        }
        __syncthreads();
        buf ^= 1;
    }

#pragma unroll
    for (int i = 0; i < 8; i++) {
        const int row = bm + ty * 8 + i;
        if (row >= M) continue;
        float* Crow = C + (size_t)row * ldc;
#pragma unroll
        for (int j = 0; j < 8; j++) {
            const int col = bn + tx * 8 + j;
            if (col >= N) continue;
            float v = acc[i][j];
            if (EPI == 1) v = softplus_f(v + bias[col]);
            if (EPI == 2) v = v + bias[col];
            Crow[col] = v;
        }
    }
}

// ---------------------------------------------------------------------------
// Depthwise causal conv (D_CONV=4) + bias + silu.
// dir 0 (forward):  xc[t] = sum_k w[k] * xi[t-3+k]
// dir 1 (backward): xc[t] = sum_k w[k] * xi[t+3-k]   (reversed-sequence conv,
//                   stored at natural t so downstream stays in natural order)
// ---------------------------------------------------------------------------
__global__ __launch_bounds__(256)
void conv_silu_kernel(const float* __restrict__ xz0,
                      const float* __restrict__ cw_f, const float* __restrict__ cb_f,
                      const float* __restrict__ cw_b, const float* __restrict__ cb_b,
                      float* __restrict__ xc0)
{
    const int dir = blockIdx.y;
    const size_t idx = (size_t)blockIdx.x * blockDim.x + threadIdx.x;  // < MT*1024
    const int d = (int)(idx & 1023);
    const size_t row = idx >> 10;            // b*SEQLEN + t
    const int t = (int)(row & (SEQLEN - 1));
    const size_t bL = row - (size_t)t;       // b*SEQLEN

    const float* xz = xz0 + (size_t)dir * (size_t)MT * 2048;
    const float* cw = dir ? cw_b : cw_f;
    const float* cb = dir ? cb_b : cb_f;

    const float4 w = __ldg((const float4*)(cw + d * 4));
    float s = cb[d];
    if (dir == 0) {
        if (t - 3 >= 0) s = fmaf(w.x, xz[(bL + (size_t)(t - 3)) * 2048 + d], s);
        if (t - 2 >= 0) s = fmaf(w.y, xz[(bL + (size_t)(t - 2)) * 2048 + d], s);
        if (t - 1 >= 0) s = fmaf(w.z, xz[(bL + (size_t)(t - 1)) * 2048 + d], s);
        s = fmaf(w.w, xz[(bL + (size_t)t) * 2048 + d], s);
    } else {
        if (t + 3 < SEQLEN) s = fmaf(w.x, xz[(bL + (size_t)(t + 3)) * 2048 + d], s);
        if (t + 2 < SEQLEN) s = fmaf(w.y, xz[(bL + (size_t)(t + 2)) * 2048 + d], s);
        if (t + 1 < SEQLEN) s = fmaf(w.z, xz[(bL + (size_t)(t + 1)) * 2048 + d], s);
        s = fmaf(w.w, xz[(bL + (size_t)t) * 2048 + d], s);
    }
    const float sv = s / (1.f + __expf(-s));   // silu
    xc0[(size_t)dir * (size_t)MT * 1024 + row * 1024 + d] = sv;
}

// ---------------------------------------------------------------------------
// Selective scan + gating.  One thread per (batch, channel); dir in grid.z.
// Fast path: if A[d,n] == A[d,0]*(n+1) (true for this model's A_log init),
// exp(dt*A[n]) = exp(dt*A[0])^(n+1) -> 1 MUFU + 15 muls per step instead of
// 16 MUFU (avoids a ~4 ms MUFU bottleneck). Generic fallback otherwise.
// Writes fused output: yg = (y_scan + xc*Dp) * silu(z), at natural time t
// (backward dir iterates t = L-1-s, which also un-reverses the output).
// ---------------------------------------------------------------------------
__global__ __launch_bounds__(128)
void scan_kernel(const float* __restrict__ dt0,
                 const float* __restrict__ dbl0,
                 const float* __restrict__ xc0,
                 const float* __restrict__ xz0,
                 const float* __restrict__ Alog_f, const float* __restrict__ Alog_b,
                 const float* __restrict__ Dp_f,   const float* __restrict__ Dp_b,
                 float* __restrict__ yg0)
{
    const int dir = blockIdx.z;
    const int b   = blockIdx.y;
    const int d   = blockIdx.x * 128 + threadIdx.x;

    const float* dt  = dt0  + (size_t)dir * (size_t)MT * 1024;
    const float* dbl = dbl0 + (size_t)dir * (size_t)MT * 64;
    const float* xc  = xc0  + (size_t)dir * (size_t)MT * 1024;
    const float* xz  = xz0  + (size_t)dir * (size_t)MT * 2048;
    float*       yg  = yg0  + (size_t)dir * (size_t)MT * 1024;
    const float* Alog = dir ? Alog_b : Alog_f;
    const float  Dv   = dir ? Dp_b[d] : Dp_f[d];

    float Aa[DSTATE];
#pragma unroll
    for (int n = 0; n < DSTATE; n++) Aa[n] = -__expf(Alog[d * DSTATE + n]);

    bool pw = true;
#pragma unroll
    for (int n = 1; n < DSTATE; n++)
        pw = pw && (fabsf(Aa[n] - Aa[0] * (float)(n + 1)) <= 1e-5f * fabsf(Aa[n]));
    pw = __all_sync(0xffffffffu, pw);

    float h[DSTATE];
#pragma unroll
    for (int n = 0; n < DSTATE; n++) h[n] = 0.f;

    for (int s = 0; s < SEQLEN; s++) {
        const int t = dir ? (SEQLEN - 1 - s) : s;
        const size_t row = (size_t)b * SEQLEN + t;

        const float dtv = dt[row * 1024 + d];
        const float xv  = xc[row * 1024 + d];
        const float zv  = xz[row * 2048 + 1024 + d];

        const float4* bc = (const float4*)(dbl + row * 64 + DTRANK);
        float Bv[DSTATE], Cv[DSTATE];
        *(float4*)&Bv[0]  = __ldg(bc + 0);
        *(float4*)&Bv[4]  = __ldg(bc + 1);
        *(float4*)&Bv[8]  = __ldg(bc + 2);
        *(float4*)&Bv[12] = __ldg(bc + 3);
        *(float4*)&Cv[0]  = __ldg(bc + 4);
        *(float4*)&Cv[4]  = __ldg(bc + 5);
        *(float4*)&Cv[8]  = __ldg(bc + 6);
        *(float4*)&Cv[12] = __ldg(bc + 7);

        const float u = dtv * xv;
        float y = 0.f;
        if (pw) {
            const float e1 = __expf(Aa[0] * dtv);
            float en = e1;
#pragma unroll
            for (int n = 0; n < DSTATE; n++) {
                h[n] = fmaf(en, h[n], u * Bv[n]);
                y = fmaf(h[n], Cv[n], y);
                en *= e1;
            }
        } else {
#pragma unroll
            for (int n = 0; n < DSTATE; n++) {
                const float en = __expf(Aa[n] * dtv);
                h[n] = fmaf(en, h[n], u * Bv[n]);
                y = fmaf(h[n], Cv[n], y);
            }
        }
        const float yo = y + xv * Dv;
        const float sg = zv / (1.f + __expf(-zv));
        yg[row * 1024 + d] = yo * sg;
    }
}

// ---------------------------------------------------------------------------
// Host launch sequence (graph-capturable: kernel launches only)
// ---------------------------------------------------------------------------
static float* symaddr(const void* sym) {
    void* p = nullptr;
    cudaGetSymbolAddress(&p, sym);
    return (float*)p;
}

extern "C" void kernel_launch(void* const* d_in, const int* in_sizes, int n_in,
                              void* d_out, int out_size)
{
    const float* x        = (const float*)d_in[0];
    const float* f_in_w   = (const float*)d_in[1];
    const float* f_conv_w = (const float*)d_in[2];
    const float* f_conv_b = (const float*)d_in[3];
    const float* f_xp_w   = (const float*)d_in[4];
    const float* f_dt_w   = (const float*)d_in[5];
    const float* f_dt_b   = (const float*)d_in[6];
    const float* f_A_log  = (const float*)d_in[7];
    const float* f_Dp     = (const float*)d_in[8];
    const float* f_out_w  = (const float*)d_in[9];
    const float* b_in_w   = (const float*)d_in[10];
    const float* b_conv_w = (const float*)d_in[11];
    const float* b_conv_b = (const float*)d_in[12];
    const float* b_xp_w   = (const float*)d_in[13];
    const float* b_dt_w   = (const float*)d_in[14];
    const float* b_dt_b   = (const float*)d_in[15];
    const float* b_A_log  = (const float*)d_in[16];
    const float* b_Dp     = (const float*)d_in[17];
    const float* b_out_w  = (const float*)d_in[18];
    const float* lin_w    = (const float*)d_in[19];
    const float* lin_b    = (const float*)d_in[20];
    float* out = (float*)d_out;

    float* xz   = symaddr(g_xz);
    float* xc   = symaddr(g_xc);
    float* dbl  = symaddr(g_dbl);
    float* dtb  = symaddr(g_dt);
    float* yg   = symaddr(g_yg);
    float* ycat = symaddr(g_ycat);

    const size_t XZ  = (size_t)MT * 2048;
    const size_t XC  = (size_t)MT * 1024;
    const size_t DBL = (size_t)MT * 64;

    const dim3 blk(256);

    // 1) xz = x @ in_w^T   (M=16384, N=2048, K=512) per direction
    gemm_nt<0><<<dim3(2048 / 128, MT / 128), blk>>>(
        x, f_in_w, xz, nullptr, MT, 2048, 512, 512, 512, 2048);
    gemm_nt<0><<<dim3(2048 / 128, MT / 128), blk>>>(
        x, b_in_w, xz + XZ, nullptr, MT, 2048, 512, 512, 512, 2048);

    // 2) depthwise conv + silu (both dirs in one launch)
    conv_silu_kernel<<<dim3((unsigned)(XC / 256), 2), blk>>>(
        xz, f_conv_w, f_conv_b, b_conv_w, b_conv_b, xc);

    // 3) dbl = xi_conv @ xp_w^T   (M=16384, N=64, K=1024)
    gemm_nt<0><<<dim3(1, MT / 128), blk>>>(
        xc, f_xp_w, dbl, nullptr, MT, 64, 1024, 1024, 1024, 64);
    gemm_nt<0><<<dim3(1, MT / 128), blk>>>(
        xc + XC, b_xp_w, dbl + DBL, nullptr, MT, 64, 1024, 1024, 1024, 64);

    // 4) dt = softplus(dbl[:, :32] @ dt_w^T + dt_b)   (M=16384, N=1024, K=32)
    gemm_nt<1><<<dim3(1024 / 128, MT / 128), blk>>>(
        dbl, f_dt_w, dtb, f_dt_b, MT, 1024, 32, 64, 32, 1024);
    gemm_nt<1><<<dim3(1024 / 128, MT / 128), blk>>>(
        dbl + DBL, b_dt_w, dtb + XC, b_dt_b, MT, 1024, 32, 64, 32, 1024);

    // 5) selective scan + gating (both dirs, 128 blocks)
    scan_kernel<<<dim3(DINNER / 128, BATCH, 2), dim3(128)>>>(
        dtb, dbl, xc, xz, f_A_log, b_A_log, f_Dp, b_Dp, yg);

    // 6) y_dir = yg @ out_w^T -> ycat[:, dir*512 : dir*512+512]
    gemm_nt<0><<<dim3(512 / 128, MT / 128), blk>>>(
        yg, f_out_w, ycat, nullptr, MT, 512, 1024, 1024, 1024, 1024);
    gemm_nt<0><<<dim3(512 / 128, MT / 128), blk>>>(
        yg + XC, b_out_w, ycat + 512, nullptr, MT, 512, 1024, 1024, 1024, 1024);

    // 7) out = ycat @ lin_w^T + lin_b   (M=16384, N=512, K=1024)
    gemm_nt<2><<<dim3(512 / 128, MT / 128), blk>>>(
        ycat, lin_w, out, lin_b, MT, 512, 1024, 1024, 1024, 512);
}

// round 8
// speedup vs baseline: 1.7856x; 1.7856x over previous
#include <cuda_runtime.h>
#include <cuda_bf16.h>
#include <cstdint>
#include <math.h>

// ---------------------------------------------------------------------------
// BiMamba: bidirectional Mamba block.
// GEMMs on tensor pipe via mma.sync bf16 with bf16x3 (hi/lo) K-split for
// fp32-class accuracy. Scan/conv in fp32 (unchanged from R7).
// B=8, L=2048, D_MODEL=512, D_INNER=1024, D_STATE=16, DT_RANK=32, D_CONV=4
// ---------------------------------------------------------------------------

#define BATCH   8
#define SEQLEN  2048
#define DMODEL  512
#define DINNER  1024
#define DSTATE  16
#define DTRANK  32
#define MT      (BATCH * SEQLEN)          // 16384 token rows

// --------------------------- fp32 scratch ----------------------------------
__device__ float g_xz  [2 * (size_t)MT * 2048];   // xi | z   (per dir)
__device__ float g_xc  [2 * (size_t)MT * 1024];   // conv+silu output
__device__ float g_dbl [2 * (size_t)MT * 64];     // dt_lowrank | B | C
__device__ float g_dt  [2 * (size_t)MT * 1024];   // softplus dt
__device__ float g_yg  [2 * (size_t)MT * 1024];   // gated scan output
__device__ float g_ycat[(size_t)MT * 1024];       // concat(y_fwd, y_bwd)

// --------------------------- bf16x3 scratch (K-split operands) --------------
// A-mode layout along K: [hi | lo | hi]; B-mode: [hi | hi | lo]
__device__ __nv_bfloat16 g_xb   [(size_t)MT * 1536];        // x
__device__ __nv_bfloat16 g_xcb  [2 * (size_t)MT * 3072];    // conv out
__device__ __nv_bfloat16 g_dblb [2 * (size_t)MT * 96];      // dt-lowrank
__device__ __nv_bfloat16 g_ygb  [2 * (size_t)MT * 3072];    // scan out
__device__ __nv_bfloat16 g_ycatb[(size_t)MT * 3072];        // concat
__device__ __nv_bfloat16 g_wb   [11599872];                 // all weights

// weight offsets inside g_wb (elements)
#define OFF_INW_F   0u
#define OFF_INW_B   3145728u
#define OFF_XPW_F   6291456u
#define OFF_XPW_B   6488064u
#define OFF_DTW_F   6684672u
#define OFF_DTW_B   6782976u
#define OFF_OUTW_F  6881280u
#define OFF_OUTW_B  8454144u
#define OFF_LINW    10027008u

// --------------------------- helpers ---------------------------------------
__device__ __forceinline__ float softplus_f(float v) {
    return v > 20.f ? v : log1pf(__expf(v));
}
__device__ __forceinline__ unsigned short bf16_bits(__nv_bfloat16 h) {
    unsigned short s; memcpy(&s, &h, 2); return s;
}

// ---------------------------------------------------------------------------
// cvt3: fp32 [R,K] (row stride in_ld) -> bf16 [R,3K].
// modeB=0 (A operand): [hi | lo | hi] ; modeB=1 (B operand): [hi | hi | lo]
// ---------------------------------------------------------------------------
__global__ __launch_bounds__(256)
void cvt3_kernel(const float* __restrict__ in, __nv_bfloat16* __restrict__ out,
                 int K, int in_ld, int total4, int modeB)
{
    const int idx = blockIdx.x * blockDim.x + threadIdx.x;
    if (idx >= total4) return;
    const int kq = K >> 2;
    const int r  = idx / kq;
    const int k  = (idx - r * kq) * 4;

    const float4 v = *(const float4*)(in + (size_t)r * in_ld + k);
    float vv[4] = {v.x, v.y, v.z, v.w};
    unsigned short hb[4], lb[4];
#pragma unroll
    for (int j = 0; j < 4; j++) {
        __nv_bfloat16 h = __float2bfloat16(vv[j]);
        float hf = __bfloat162float(h);
        __nv_bfloat16 l = __float2bfloat16(vv[j] - hf);
        hb[j] = bf16_bits(h); lb[j] = bf16_bits(l);
    }
    uint2 H, L;
    H.x = (uint32_t)hb[0] | ((uint32_t)hb[1] << 16);
    H.y = (uint32_t)hb[2] | ((uint32_t)hb[3] << 16);
    L.x = (uint32_t)lb[0] | ((uint32_t)lb[1] << 16);
    L.y = (uint32_t)lb[2] | ((uint32_t)lb[3] << 16);

    __nv_bfloat16* ob = out + (size_t)r * (3 * K) + k;
    *(uint2*)(ob)         = H;
    *(uint2*)(ob + K)     = modeB ? H : L;
    *(uint2*)(ob + 2 * K) = modeB ? L : H;
}

// ---------------------------------------------------------------------------
// bf16 NT tensor-core GEMM: C[m,n] = sum_k A[m,k]*B[n,k]
// A:[M,K3] bf16 row-major, B:[N,K3] bf16 row-major, C fp32 [*,ldc].
// 128x128x32 tile, 256 thr (8 warps: 4x2), m16n8k16 mma, cp.async 3-stage.
// EPI: 0 none, 1 softplus(v+bias[n]), 2 v+bias[n]
// Requires: M % 128 == 0, K3 % 32 == 0, K3 >= 96.
// ---------------------------------------------------------------------------
#define GSTAGES 3

__device__ __forceinline__ void cp_async16(uint32_t s, const void* g, int sz) {
    asm volatile("cp.async.cg.shared.global [%0], [%1], 16, %2;\n"
                 :: "r"(s), "l"(g), "r"(sz));
}
__device__ __forceinline__ void ldsm_x4(uint32_t& r0, uint32_t& r1,
                                        uint32_t& r2, uint32_t& r3, uint32_t addr) {
    asm volatile("ldmatrix.sync.aligned.m8n8.x4.shared.b16 {%0,%1,%2,%3}, [%4];"
                 : "=r"(r0), "=r"(r1), "=r"(r2), "=r"(r3) : "r"(addr));
}
__device__ __forceinline__ void mma_bf16(float* c, const uint32_t* a, const uint32_t* b) {
    asm volatile("mma.sync.aligned.m16n8k16.row.col.f32.bf16.bf16.f32 "
                 "{%0,%1,%2,%3},{%4,%5,%6,%7},{%8,%9},{%0,%1,%2,%3};"
                 : "+f"(c[0]), "+f"(c[1]), "+f"(c[2]), "+f"(c[3])
                 : "r"(a[0]), "r"(a[1]), "r"(a[2]), "r"(a[3]),
                   "r"(b[0]), "r"(b[1]));
}

// swizzled chunk position (16B units) within a 128x32 bf16 tile
__device__ __forceinline__ int chunk_pos(int row, int c) {
    return row * 4 + (c ^ ((row >> 1) & 3));
}

template <int EPI>
__global__ __launch_bounds__(256, 2)
void bgemm_nt(const __nv_bfloat16* __restrict__ A,
              const __nv_bfloat16* __restrict__ B,
              float* __restrict__ C, const float* __restrict__ bias,
              int M, int N, int K3, int ldc)
{
    __shared__ __align__(16) __nv_bfloat16 smem[GSTAGES * 2 * 128 * 32];
    const uint32_t sbase = (uint32_t)__cvta_generic_to_shared(smem);

    const int tid  = threadIdx.x;
    const int bm   = blockIdx.y * 128;
    const int bn   = blockIdx.x * 128;
    const int warp = tid >> 5;
    const int lane = tid & 31;
    const int wm   = (warp >> 1) * 32;   // warp M offset (0,32,64,96)
    const int wn   = (warp & 1) * 64;    // warp N offset (0,64)

    // loader indices: each thread moves 2 A-chunks + 2 B-chunks per tile
    const int l_row0 = tid >> 2,            l_c0 = tid & 3;
    const int l_row1 = (tid + 256) >> 2,    l_c1 = (tid + 256) & 3;

    // ldmatrix row indices (fixed per lane)
    const int lrow = (lane & 7) + 8 * ((lane >> 3) & 1);
    const int lc_hi = (lane >> 4);       // 0/1 -> k sub-chunk

    float acc[2][8][4];
#pragma unroll
    for (int mi = 0; mi < 2; mi++)
#pragma unroll
        for (int ni = 0; ni < 8; ni++)
#pragma unroll
            for (int q = 0; q < 4; q++) acc[mi][ni][q] = 0.f;

    const int K3T = K3 >> 5;

    auto load_tile = [&](int kt, int s) {
        const int k0 = kt * 32;
        {   // chunk 0
            const int row = l_row0, c = l_c0;
            cp_async16(sbase + (uint32_t)(s * 1024 + chunk_pos(row, c)) * 16,
                       A + (size_t)(bm + row) * K3 + k0 + c * 8, 16);
            const int brow = bn + row;
            const int bcl  = brow < N ? brow : (N - 1);
            cp_async16(sbase + (uint32_t)(s * 1024 + 512 + chunk_pos(row, c)) * 16,
                       B + (size_t)bcl * K3 + k0 + c * 8, brow < N ? 16 : 0);
        }
        {   // chunk 1
            const int row = l_row1, c = l_c1;
            cp_async16(sbase + (uint32_t)(s * 1024 + chunk_pos(row, c)) * 16,
                       A + (size_t)(bm + row) * K3 + k0 + c * 8, 16);
            const int brow = bn + row;
            const int bcl  = brow < N ? brow : (N - 1);
            cp_async16(sbase + (uint32_t)(s * 1024 + 512 + chunk_pos(row, c)) * 16,
                       B + (size_t)bcl * K3 + k0 + c * 8, brow < N ? 16 : 0);
        }
    };

    load_tile(0, 0); asm volatile("cp.async.commit_group;");
    load_tile(1, 1); asm volatile("cp.async.commit_group;");

    for (int kt = 0; kt < K3T; kt++) {
        asm volatile("cp.async.wait_group 1;");
        __syncthreads();

        if (kt + 2 < K3T) load_tile(kt + 2, (kt + 2) % GSTAGES);
        asm volatile("cp.async.commit_group;");

        const int s = kt % GSTAGES;
        const uint32_t abase = sbase + (uint32_t)(s * 1024) * 16;
        const uint32_t bbase = sbase + (uint32_t)(s * 1024 + 512) * 16;

#pragma unroll
        for (int ks = 0; ks < 2; ks++) {
            const int c = ks * 2 + lc_hi;
            uint32_t af[2][4];
#pragma unroll
            for (int mi = 0; mi < 2; mi++) {
                const int r = wm + mi * 16 + lrow;
                ldsm_x4(af[mi][0], af[mi][1], af[mi][2], af[mi][3],
                        abase + (uint32_t)chunk_pos(r, c) * 16);
            }
            uint32_t bf[8][2];
#pragma unroll
            for (int pi = 0; pi < 4; pi++) {
                const int r = wn + pi * 16 + lrow;
                uint32_t q0, q1, q2, q3;
                ldsm_x4(q0, q1, q2, q3, bbase + (uint32_t)chunk_pos(r, c) * 16);
                bf[2 * pi][0] = q0; bf[2 * pi][1] = q2;
                bf[2 * pi + 1][0] = q1; bf[2 * pi + 1][1] = q3;
            }
#pragma unroll
            for (int mi = 0; mi < 2; mi++)
#pragma unroll
                for (int ni = 0; ni < 8; ni++)
                    mma_bf16(acc[mi][ni], af[mi], bf[ni]);
        }
    }

    // epilogue
    const int erow = (lane >> 2);
    const int ecol = (lane & 3) * 2;
#pragma unroll
    for (int mi = 0; mi < 2; mi++) {
#pragma unroll
        for (int ni = 0; ni < 8; ni++) {
            const int col = bn + wn + ni * 8 + ecol;
            if (col >= N) continue;
            const int row = bm + wm + mi * 16 + erow;
            float v0 = acc[mi][ni][0], v1 = acc[mi][ni][1];
            float v2 = acc[mi][ni][2], v3 = acc[mi][ni][3];
            if (EPI == 1) {
                const float b0 = bias[col], b1 = bias[col + 1];
                v0 = softplus_f(v0 + b0); v1 = softplus_f(v1 + b1);
                v2 = softplus_f(v2 + b0); v3 = softplus_f(v3 + b1);
            }
            if (EPI == 2) {
                const float b0 = bias[col], b1 = bias[col + 1];
                v0 += b0; v1 += b1; v2 += b0; v3 += b1;
            }
            *(float2*)(C + (size_t)row * ldc + col)       = make_float2(v0, v1);
            *(float2*)(C + (size_t)(row + 8) * ldc + col) = make_float2(v2, v3);
        }
    }
}

// ---------------------------------------------------------------------------
// Depthwise causal conv (D_CONV=4) + bias + silu. (unchanged from R7)
// ---------------------------------------------------------------------------
__global__ __launch_bounds__(256)
void conv_silu_kernel(const float* __restrict__ xz0,
                      const float* __restrict__ cw_f, const float* __restrict__ cb_f,
                      const float* __restrict__ cw_b, const float* __restrict__ cb_b,
                      float* __restrict__ xc0)
{
    const int dir = blockIdx.y;
    const size_t idx = (size_t)blockIdx.x * blockDim.x + threadIdx.x;
    const int d = (int)(idx & 1023);
    const size_t row = idx >> 10;
    const int t = (int)(row & (SEQLEN - 1));
    const size_t bL = row - (size_t)t;

    const float* xz = xz0 + (size_t)dir * (size_t)MT * 2048;
    const float* cw = dir ? cw_b : cw_f;
    const float* cb = dir ? cb_b : cb_f;

    const float4 w = __ldg((const float4*)(cw + d * 4));
    float s = cb[d];
    if (dir == 0) {
        if (t - 3 >= 0) s = fmaf(w.x, xz[(bL + (size_t)(t - 3)) * 2048 + d], s);
        if (t - 2 >= 0) s = fmaf(w.y, xz[(bL + (size_t)(t - 2)) * 2048 + d], s);
        if (t - 1 >= 0) s = fmaf(w.z, xz[(bL + (size_t)(t - 1)) * 2048 + d], s);
        s = fmaf(w.w, xz[(bL + (size_t)t) * 2048 + d], s);
    } else {
        if (t + 3 < SEQLEN) s = fmaf(w.x, xz[(bL + (size_t)(t + 3)) * 2048 + d], s);
        if (t + 2 < SEQLEN) s = fmaf(w.y, xz[(bL + (size_t)(t + 2)) * 2048 + d], s);
        if (t + 1 < SEQLEN) s = fmaf(w.z, xz[(bL + (size_t)(t + 1)) * 2048 + d], s);
        s = fmaf(w.w, xz[(bL + (size_t)t) * 2048 + d], s);
    }
    const float sv = s / (1.f + __expf(-s));
    xc0[(size_t)dir * (size_t)MT * 1024 + row * 1024 + d] = sv;
}

// ---------------------------------------------------------------------------
// Selective scan + gating. (unchanged from R7; power-chain exp fast path)
// ---------------------------------------------------------------------------
__global__ __launch_bounds__(128)
void scan_kernel(const float* __restrict__ dt0,
                 const float* __restrict__ dbl0,
                 const float* __restrict__ xc0,
                 const float* __restrict__ xz0,
                 const float* __restrict__ Alog_f, const float* __restrict__ Alog_b,
                 const float* __restrict__ Dp_f,   const float* __restrict__ Dp_b,
                 float* __restrict__ yg0)
{
    const int dir = blockIdx.z;
    const int b   = blockIdx.y;
    const int d   = blockIdx.x * 128 + threadIdx.x;

    const float* dt  = dt0  + (size_t)dir * (size_t)MT * 1024;
    const float* dbl = dbl0 + (size_t)dir * (size_t)MT * 64;
    const float* xc  = xc0  + (size_t)dir * (size_t)MT * 1024;
    const float* xz  = xz0  + (size_t)dir * (size_t)MT * 2048;
    float*       yg  = yg0  + (size_t)dir * (size_t)MT * 1024;
    const float* Alog = dir ? Alog_b : Alog_f;
    const float  Dv   = dir ? Dp_b[d] : Dp_f[d];

    float Aa[DSTATE];
#pragma unroll
    for (int n = 0; n < DSTATE; n++) Aa[n] = -__expf(Alog[d * DSTATE + n]);

    bool pw = true;
#pragma unroll
    for (int n = 1; n < DSTATE; n++)
        pw = pw && (fabsf(Aa[n] - Aa[0] * (float)(n + 1)) <= 1e-5f * fabsf(Aa[n]));
    pw = __all_sync(0xffffffffu, pw);

    float h[DSTATE];
#pragma unroll
    for (int n = 0; n < DSTATE; n++) h[n] = 0.f;

    for (int s = 0; s < SEQLEN; s++) {
        const int t = dir ? (SEQLEN - 1 - s) : s;
        const size_t row = (size_t)b * SEQLEN + t;

        const float dtv = dt[row * 1024 + d];
        const float xv  = xc[row * 1024 + d];
        const float zv  = xz[row * 2048 + 1024 + d];

        const float4* bc = (const float4*)(dbl + row * 64 + DTRANK);
        float Bv[DSTATE], Cv[DSTATE];
        *(float4*)&Bv[0]  = __ldg(bc + 0);
        *(float4*)&Bv[4]  = __ldg(bc + 1);
        *(float4*)&Bv[8]  = __ldg(bc + 2);
        *(float4*)&Bv[12] = __ldg(bc + 3);
        *(float4*)&Cv[0]  = __ldg(bc + 4);
        *(float4*)&Cv[4]  = __ldg(bc + 5);
        *(float4*)&Cv[8]  = __ldg(bc + 6);
        *(float4*)&Cv[12] = __ldg(bc + 7);

        const float u = dtv * xv;
        float y = 0.f;
        if (pw) {
            const float e1 = __expf(Aa[0] * dtv);
            float en = e1;
#pragma unroll
            for (int n = 0; n < DSTATE; n++) {
                h[n] = fmaf(en, h[n], u * Bv[n]);
                y = fmaf(h[n], Cv[n], y);
                en *= e1;
            }
        } else {
#pragma unroll
            for (int n = 0; n < DSTATE; n++) {
                const float en = __expf(Aa[n] * dtv);
                h[n] = fmaf(en, h[n], u * Bv[n]);
                y = fmaf(h[n], Cv[n], y);
            }
        }
        const float yo = y + xv * Dv;
        const float sg = zv / (1.f + __expf(-zv));
        yg[row * 1024 + d] = yo * sg;
    }
}

// ---------------------------------------------------------------------------
// Host launch sequence (graph-capturable: kernel launches only)
// ---------------------------------------------------------------------------
static float* symaddrf(const void* sym) {
    void* p = nullptr; cudaGetSymbolAddress(&p, sym); return (float*)p;
}
static __nv_bfloat16* symaddrb(const void* sym) {
    void* p = nullptr; cudaGetSymbolAddress(&p, sym); return (__nv_bfloat16*)p;
}

static inline void cvt3(const float* in, __nv_bfloat16* out, int R, int K,
                        int in_ld, int modeB) {
    const int total4 = R * (K / 4);
    cvt3_kernel<<<(total4 + 255) / 256, 256>>>(in, out, K, in_ld, total4, modeB);
}

extern "C" void kernel_launch(void* const* d_in, const int* in_sizes, int n_in,
                              void* d_out, int out_size)
{
    const float* x        = (const float*)d_in[0];
    const float* f_in_w   = (const float*)d_in[1];
    const float* f_conv_w = (const float*)d_in[2];
    const float* f_conv_b = (const float*)d_in[3];
    const float* f_xp_w   = (const float*)d_in[4];
    const float* f_dt_w   = (const float*)d_in[5];
    const float* f_dt_b   = (const float*)d_in[6];
    const float* f_A_log  = (const float*)d_in[7];
    const float* f_Dp     = (const float*)d_in[8];
    const float* f_out_w  = (const float*)d_in[9];
    const float* b_in_w   = (const float*)d_in[10];
    const float* b_conv_w = (const float*)d_in[11];
    const float* b_conv_b = (const float*)d_in[12];
    const float* b_xp_w   = (const float*)d_in[13];
    const float* b_dt_w   = (const float*)d_in[14];
    const float* b_dt_b   = (const float*)d_in[15];
    const float* b_A_log  = (const float*)d_in[16];
    const float* b_Dp     = (const float*)d_in[17];
    const float* b_out_w  = (const float*)d_in[18];
    const float* lin_w    = (const float*)d_in[19];
    const float* lin_b    = (const float*)d_in[20];
    float* out = (float*)d_out;

    float* xz   = symaddrf(g_xz);
    float* xc   = symaddrf(g_xc);
    float* dbl  = symaddrf(g_dbl);
    float* dtb  = symaddrf(g_dt);
    float* yg   = symaddrf(g_yg);
    float* ycat = symaddrf(g_ycat);

    __nv_bfloat16* xb    = symaddrb(g_xb);
    __nv_bfloat16* xcb   = symaddrb(g_xcb);
    __nv_bfloat16* dblb  = symaddrb(g_dblb);
    __nv_bfloat16* ygb   = symaddrb(g_ygb);
    __nv_bfloat16* ycatb = symaddrb(g_ycatb);
    __nv_bfloat16* wb    = symaddrb(g_wb);

    const size_t XZ   = (size_t)MT * 2048;
    const size_t XC   = (size_t)MT * 1024;
    const size_t DBL  = (size_t)MT * 64;
    const size_t XCB  = (size_t)MT * 3072;
    const size_t DBLB = (size_t)MT * 96;

    const dim3 blk(256);

    // 0) operand conversions (weights B-mode, x A-mode)
    cvt3(x,       xb,               MT,   512,  512,  0);
    cvt3(f_in_w,  wb + OFF_INW_F,   2048, 512,  512,  1);
    cvt3(b_in_w,  wb + OFF_INW_B,   2048, 512,  512,  1);
    cvt3(f_xp_w,  wb + OFF_XPW_F,   64,   1024, 1024, 1);
    cvt3(b_xp_w,  wb + OFF_XPW_B,   64,   1024, 1024, 1);
    cvt3(f_dt_w,  wb + OFF_DTW_F,   1024, 32,   32,   1);
    cvt3(b_dt_w,  wb + OFF_DTW_B,   1024, 32,   32,   1);
    cvt3(f_out_w, wb + OFF_OUTW_F,  512,  1024, 1024, 1);
    cvt3(b_out_w, wb + OFF_OUTW_B,  512,  1024, 1024, 1);
    cvt3(lin_w,   wb + OFF_LINW,    512,  1024, 1024, 1);

    // 1) xz = x @ in_w^T  (M=16384, N=2048, K3=1536) per direction
    bgemm_nt<0><<<dim3(2048 / 128, MT / 128), blk>>>(
        xb, wb + OFF_INW_F, xz,      nullptr, MT, 2048, 1536, 2048);
    bgemm_nt<0><<<dim3(2048 / 128, MT / 128), blk>>>(
        xb, wb + OFF_INW_B, xz + XZ, nullptr, MT, 2048, 1536, 2048);

    // 2) depthwise conv + silu (both dirs)
    conv_silu_kernel<<<dim3((unsigned)(XC / 256), 2), blk>>>(
        xz, f_conv_w, f_conv_b, b_conv_w, b_conv_b, xc);

    // 3) convert conv output, then dbl = xc @ xp_w^T (N=64, K3=3072)
    cvt3(xc,      xcb,       MT, 1024, 1024, 0);
    cvt3(xc + XC, xcb + XCB, MT, 1024, 1024, 0);
    bgemm_nt<0><<<dim3(1, MT / 128), blk>>>(
        xcb,       wb + OFF_XPW_F, dbl,       nullptr, MT, 64, 3072, 64);
    bgemm_nt<0><<<dim3(1, MT / 128), blk>>>(
        xcb + XCB, wb + OFF_XPW_B, dbl + DBL, nullptr, MT, 64, 3072, 64);

    // 4) dt = softplus(dbl[:, :32] @ dt_w^T + dt_b)  (N=1024, K3=96)
    cvt3(dbl,       dblb,        MT, 32, 64, 0);
    cvt3(dbl + DBL, dblb + DBLB, MT, 32, 64, 0);
    bgemm_nt<1><<<dim3(1024 / 128, MT / 128), blk>>>(
        dblb,        wb + OFF_DTW_F, dtb,      f_dt_b, MT, 1024, 96, 1024);
    bgemm_nt<1><<<dim3(1024 / 128, MT / 128), blk>>>(
        dblb + DBLB, wb + OFF_DTW_B, dtb + XC, b_dt_b, MT, 1024, 96, 1024);

    // 5) selective scan + gating (both dirs)
    scan_kernel<<<dim3(DINNER / 128, BATCH, 2), dim3(128)>>>(
        dtb, dbl, xc, xz, f_A_log, b_A_log, f_Dp, b_Dp, yg);

    // 6) y_dir = yg @ out_w^T -> ycat[:, dir*512:+512]  (N=512, K3=3072)
    cvt3(yg,      ygb,       MT, 1024, 1024, 0);
    cvt3(yg + XC, ygb + XCB, MT, 1024, 1024, 0);
    bgemm_nt<0><<<dim3(512 / 128, MT / 128), blk>>>(
        ygb,       wb + OFF_OUTW_F, ycat,       nullptr, MT, 512, 3072, 1024);
    bgemm_nt<0><<<dim3(512 / 128, MT / 128), blk>>>(
        ygb + XCB, wb + OFF_OUTW_B, ycat + 512, nullptr, MT, 512, 3072, 1024);

    // 7) out = ycat @ lin_w^T + lin_b  (N=512, K3=3072)
    cvt3(ycat, ycatb, MT, 1024, 1024, 0);
    bgemm_nt<2><<<dim3(512 / 128, MT / 128), blk>>>(
        ycatb, wb + OFF_LINW, out, lin_b, MT, 512, 3072, 512);
}

// round 13
// speedup vs baseline: 2.5809x; 1.4454x over previous
#include <cuda_runtime.h>
#include <cuda_bf16.h>
#include <cstdint>
#include <math.h>

// ---------------------------------------------------------------------------
// BiMamba: bidirectional Mamba block.
// GEMMs on mma.sync bf16 (bf16x3 K-split => fp32-class accuracy).
// 64x64 warp tiles (smem-traffic-optimal), dir-merged launches (grid.z=2),
// cp.async-pipelined selective scan, fused bf16x3 conversions.
// B=8, L=2048, D_MODEL=512, D_INNER=1024, D_STATE=16, DT_RANK=32, D_CONV=4
// ---------------------------------------------------------------------------

#define BATCH   8
#define SEQLEN  2048
#define DSTATE  16
#define DTRANK  32
#define MT      (BATCH * SEQLEN)          // 16384 token rows

// --------------------------- fp32 scratch ----------------------------------
__device__ float g_xz  [2 * (size_t)MT * 2048];   // xi | z   (per dir)
__device__ float g_xc  [2 * (size_t)MT * 1024];   // conv+silu output (fp32, scan input)
__device__ float g_dbl [2 * (size_t)MT * 64];     // dt_lowrank | B | C
__device__ float g_dt  [2 * (size_t)MT * 1024];   // softplus dt

// --------------------------- bf16x3 scratch (K-split operands) --------------
// A-mode layout along K: [hi | lo | hi]; B-mode: [hi | hi | lo]
__device__ __nv_bfloat16 g_xb   [(size_t)MT * 1536];        // x
__device__ __nv_bfloat16 g_xcb  [2 * (size_t)MT * 3072];    // conv out
__device__ __nv_bfloat16 g_dblb [2 * (size_t)MT * 96];      // dt-lowrank
__device__ __nv_bfloat16 g_ygb  [2 * (size_t)MT * 3072];    // scan out
__device__ __nv_bfloat16 g_ycatb[(size_t)MT * 3072];        // concat (A-mode, KO=1024)
__device__ __nv_bfloat16 g_wb   [11599872];                 // all weights (B-mode)

// weight offsets inside g_wb (elements)
#define OFF_INW_F   0u
#define OFF_INW_B   3145728u
#define OFF_XPW_F   6291456u
#define OFF_XPW_B   6488064u
#define OFF_DTW_F   6684672u
#define OFF_DTW_B   6782976u
#define OFF_OUTW_F  6881280u
#define OFF_OUTW_B  8454144u
#define OFF_LINW    10027008u

// --------------------------- helpers ---------------------------------------
__device__ __forceinline__ float softplus_f(float v) {
    return v > 20.f ? v : log1pf(__expf(v));
}
__device__ __forceinline__ unsigned short bf16_bits(__nv_bfloat16 h) {
    unsigned short s; memcpy(&s, &h, 2); return s;
}
__device__ __forceinline__ uint32_t smem_u32(const void* p) {
    return (uint32_t)__cvta_generic_to_shared(p);
}
__device__ __forceinline__ void cp_async16(uint32_t s, const void* g, int sz) {
    asm volatile("cp.async.cg.shared.global [%0], [%1], 16, %2;\n"
                 :: "r"(s), "l"(g), "r"(sz));
}
__device__ __forceinline__ void cp_async16ca(uint32_t s, const void* g) {
    asm volatile("cp.async.ca.shared.global [%0], [%1], 16;\n"
                 :: "r"(s), "l"(g));
}
__device__ __forceinline__ void ldsm_x4(uint32_t& r0, uint32_t& r1,
                                        uint32_t& r2, uint32_t& r3, uint32_t addr) {
    asm volatile("ldmatrix.sync.aligned.m8n8.x4.shared.b16 {%0,%1,%2,%3}, [%4];"
                 : "=r"(r0), "=r"(r1), "=r"(r2), "=r"(r3) : "r"(addr));
}
__device__ __forceinline__ void mma_bf16(float* c, const uint32_t* a, const uint32_t* b) {
    asm volatile("mma.sync.aligned.m16n8k16.row.col.f32.bf16.bf16.f32 "
                 "{%0,%1,%2,%3},{%4,%5,%6,%7},{%8,%9},{%0,%1,%2,%3};"
                 : "+f"(c[0]), "+f"(c[1]), "+f"(c[2]), "+f"(c[3])
                 : "r"(a[0]), "r"(a[1]), "r"(a[2]), "r"(a[3]),
                   "r"(b[0]), "r"(b[1]));
}
// swizzled chunk position (16B units) within a 128x32 bf16 tile
__device__ __forceinline__ int chunk_pos(int row, int c) {
    return row * 4 + (c ^ ((row >> 1) & 3));
}

// ---------------------------------------------------------------------------
// cvt3: fp32 [R,K] (row stride in_ld) -> bf16 [R,3K].
// modeB=0 (A operand): [hi | lo | hi] ; modeB=1 (B operand): [hi | hi | lo]
// ---------------------------------------------------------------------------
__global__ __launch_bounds__(256)
void cvt3_kernel(const float* __restrict__ in, __nv_bfloat16* __restrict__ out,
                 int K, int in_ld, int total4, int modeB)
{
    const int idx = blockIdx.x * blockDim.x + threadIdx.x;
    if (idx >= total4) return;
    const int kq = K >> 2;
    const int r  = idx / kq;
    const int k  = (idx - r * kq) * 4;

    const float4 v = *(const float4*)(in + (size_t)r * in_ld + k);
    float vv[4] = {v.x, v.y, v.z, v.w};
    unsigned short hb[4], lb[4];
#pragma unroll
    for (int j = 0; j < 4; j++) {
        __nv_bfloat16 h = __float2bfloat16(vv[j]);
        float hf = __bfloat162float(h);
        __nv_bfloat16 l = __float2bfloat16(vv[j] - hf);
        hb[j] = bf16_bits(h); lb[j] = bf16_bits(l);
    }
    uint2 H, L;
    H.x = (uint32_t)hb[0] | ((uint32_t)hb[1] << 16);
    H.y = (uint32_t)hb[2] | ((uint32_t)hb[3] << 16);
    L.x = (uint32_t)lb[0] | ((uint32_t)lb[1] << 16);
    L.y = (uint32_t)lb[2] | ((uint32_t)lb[3] << 16);

    __nv_bfloat16* ob = out + (size_t)r * (3 * K) + k;
    *(uint2*)(ob)         = H;
    *(uint2*)(ob + K)     = modeB ? H : L;
    *(uint2*)(ob + 2 * K) = modeB ? L : H;
}

// ===========================================================================
// bgemm_w: mma.sync NT GEMM, 128x128 CTA tile, 4 warps, 64x64 warp tile.
// A:[M,K3], B:[N,K3] bf16 row-major. grid.z = dir (pointer strides sA/sB/sC).
// EPI: 0 none(fp32 C), 1 softplus(v+bias[n])(fp32), 2 v+bias[n](fp32)
// OUTB=1: write bf16x3 A-mode into bf16 C at [row, obase+z*obstep+col] over KO.
// Requires M%128==0, N%128==0, K3%32==0, K3>=96.
// ===========================================================================
template <int EPI, int OUTB>
__global__ __launch_bounds__(128, 2)
void bgemm_w(const __nv_bfloat16* __restrict__ A0,
             const __nv_bfloat16* __restrict__ B0,
             void* __restrict__ C0,
             const float* __restrict__ biasf, const float* __restrict__ biasb,
             int N, int K3, int ldc,
             size_t sA, size_t sB, size_t sC,
             int obase, int obstep, int KO)
{
    __shared__ __align__(16) __nv_bfloat16 smem[3 * 2 * 128 * 32];  // 48KB
    const uint32_t sbase = smem_u32(smem);

    const int z = blockIdx.z;
    const __nv_bfloat16* A = A0 + (size_t)z * sA;
    const __nv_bfloat16* B = B0 + (size_t)z * sB;
    const float* bias = z ? biasb : biasf;

    const int tid  = threadIdx.x;
    const int warp = tid >> 5;
    const int lane = tid & 31;
    const int bm   = blockIdx.y * 128;
    const int bn   = blockIdx.x * 128;
    const int wm   = (warp & 1) * 64;
    const int wn   = (warp >> 1) * 64;
    const int lrow = lane & 15;
    const int lc_hi = lane >> 4;

    float acc[4][8][4];
#pragma unroll
    for (int mi = 0; mi < 4; mi++)
#pragma unroll
        for (int ni = 0; ni < 8; ni++)
#pragma unroll
            for (int q = 0; q < 4; q++) acc[mi][ni][q] = 0.f;

    const int K3T = K3 >> 5;

    auto load_tile = [&](int kt, int s) {
        const int k0 = kt * 32;
#pragma unroll
        for (int i = 0; i < 4; i++) {
            const int idx = tid + i * 128;
            const int row = idx >> 2;
            const int c   = idx & 3;
            cp_async16(sbase + (uint32_t)(s * 1024 + chunk_pos(row, c)) * 16,
                       A + (size_t)(bm + row) * K3 + k0 + c * 8, 16);
            cp_async16(sbase + (uint32_t)(s * 1024 + 512 + chunk_pos(row, c)) * 16,
                       B + (size_t)(bn + row) * K3 + k0 + c * 8, 16);
        }
    };

    load_tile(0, 0); asm volatile("cp.async.commit_group;");
    load_tile(1, 1); asm volatile("cp.async.commit_group;");

    for (int kt = 0; kt < K3T; kt++) {
        asm volatile("cp.async.wait_group 1;");
        __syncthreads();

        if (kt + 2 < K3T) load_tile(kt + 2, (kt + 2) % 3);
        asm volatile("cp.async.commit_group;");

        const int s = kt % 3;
        const uint32_t abase = sbase + (uint32_t)(s * 1024) * 16;
        const uint32_t bbase = sbase + (uint32_t)(s * 1024 + 512) * 16;

#pragma unroll
        for (int ks = 0; ks < 2; ks++) {
            const int c = ks * 2 + lc_hi;
            uint32_t af[4][4];
#pragma unroll
            for (int mi = 0; mi < 4; mi++) {
                const int r = wm + mi * 16 + lrow;
                ldsm_x4(af[mi][0], af[mi][1], af[mi][2], af[mi][3],
                        abase + (uint32_t)chunk_pos(r, c) * 16);
            }
            uint32_t bf[8][2];
#pragma unroll
            for (int pi = 0; pi < 4; pi++) {
                const int r = wn + pi * 16 + lrow;
                uint32_t q0, q1, q2, q3;
                ldsm_x4(q0, q1, q2, q3, bbase + (uint32_t)chunk_pos(r, c) * 16);
                bf[2 * pi][0] = q0; bf[2 * pi][1] = q2;
                bf[2 * pi + 1][0] = q1; bf[2 * pi + 1][1] = q3;
            }
#pragma unroll
            for (int mi = 0; mi < 4; mi++)
#pragma unroll
                for (int ni = 0; ni < 8; ni++)
                    mma_bf16(acc[mi][ni], af[mi], bf[ni]);
        }
    }

    // epilogue
    const int erow = (lane >> 2);
    const int ecol = (lane & 3) * 2;

    if (OUTB) {
        __nv_bfloat16* Cb = (__nv_bfloat16*)C0;
        const int ob  = obase + z * obstep;
        const int ld3 = 3 * KO;
#pragma unroll
        for (int mi = 0; mi < 4; mi++) {
#pragma unroll
            for (int ni = 0; ni < 8; ni++) {
                const int col = ob + bn + wn + ni * 8 + ecol;
                const int row = bm + wm + mi * 16 + erow;
#pragma unroll
                for (int rr = 0; rr < 2; rr++) {
                    const float va = acc[mi][ni][rr * 2 + 0];
                    const float vb = acc[mi][ni][rr * 2 + 1];
                    __nv_bfloat16 ha = __float2bfloat16(va);
                    __nv_bfloat16 hb = __float2bfloat16(vb);
                    __nv_bfloat16 la = __float2bfloat16(va - __bfloat162float(ha));
                    __nv_bfloat16 lb = __float2bfloat16(vb - __bfloat162float(hb));
                    const uint32_t hp = (uint32_t)bf16_bits(ha) | ((uint32_t)bf16_bits(hb) << 16);
                    const uint32_t lp = (uint32_t)bf16_bits(la) | ((uint32_t)bf16_bits(lb) << 16);
                    __nv_bfloat16* base = Cb + (size_t)(row + rr * 8) * ld3 + col;
                    *(uint32_t*)(base)          = hp;
                    *(uint32_t*)(base + KO)     = lp;
                    *(uint32_t*)(base + 2 * KO) = hp;
                }
            }
        }
    } else {
        float* C = (float*)C0 + (size_t)z * sC;
#pragma unroll
        for (int mi = 0; mi < 4; mi++) {
#pragma unroll
            for (int ni = 0; ni < 8; ni++) {
                const int col = bn + wn + ni * 8 + ecol;
                const int row = bm + wm + mi * 16 + erow;
                float v0 = acc[mi][ni][0], v1 = acc[mi][ni][1];
                float v2 = acc[mi][ni][2], v3 = acc[mi][ni][3];
                if (EPI == 1) {
                    const float b0 = bias[col], b1 = bias[col + 1];
                    v0 = softplus_f(v0 + b0); v1 = softplus_f(v1 + b1);
                    v2 = softplus_f(v2 + b0); v3 = softplus_f(v3 + b1);
                }
                if (EPI == 2) {
                    const float b0 = bias[col], b1 = bias[col + 1];
                    v0 += b0; v1 += b1; v2 += b0; v3 += b1;
                }
                *(float2*)(C + (size_t)row * ldc + col)       = make_float2(v0, v1);
                *(float2*)(C + (size_t)(row + 8) * ldc + col) = make_float2(v2, v3);
            }
        }
    }
}

// ---------------------------------------------------------------------------
// bgemm_nt: 128x128 / 8-warp mma.sync kernel kept ONLY for the skinny xp GEMM
// (N=64, needs col clamps). grid.z = dir.
// ---------------------------------------------------------------------------
__global__ __launch_bounds__(256, 2)
void bgemm_nt(const __nv_bfloat16* __restrict__ A0,
              const __nv_bfloat16* __restrict__ B0,
              float* __restrict__ C0,
              int M, int N, int K3, int ldc,
              size_t sA, size_t sB, size_t sC)
{
    __shared__ __align__(16) __nv_bfloat16 smem[3 * 2 * 128 * 32];
    const uint32_t sbase = smem_u32(smem);

    const int z = blockIdx.z;
    const __nv_bfloat16* A = A0 + (size_t)z * sA;
    const __nv_bfloat16* B = B0 + (size_t)z * sB;
    float* C = C0 + (size_t)z * sC;

    const int tid  = threadIdx.x;
    const int bm   = blockIdx.y * 128;
    const int bn   = blockIdx.x * 128;
    const int warp = tid >> 5;
    const int lane = tid & 31;
    const int wm   = (warp >> 1) * 32;
    const int wn   = (warp & 1) * 64;

    const int l_row0 = tid >> 1;
    const int l_c0   = (tid & 1) * 2;   // chunks c0, c0+1

    const int lrow = lane & 15;
    const int lc_hi = lane >> 4;

    float acc[2][8][4];
#pragma unroll
    for (int mi = 0; mi < 2; mi++)
#pragma unroll
        for (int ni = 0; ni < 8; ni++)
#pragma unroll
            for (int q = 0; q < 4; q++) acc[mi][ni][q] = 0.f;

    const int K3T = K3 >> 5;

    auto load_tile = [&](int kt, int s) {
        const int k0 = kt * 32;
#pragma unroll
        for (int cc = 0; cc < 2; cc++) {
            const int row = l_row0, c = l_c0 + cc;
            cp_async16(sbase + (uint32_t)(s * 1024 + chunk_pos(row, c)) * 16,
                       A + (size_t)(bm + row) * K3 + k0 + c * 8, 16);
            const int brow = bn + row;
            const int bcl  = brow < N ? brow : (N - 1);
            cp_async16(sbase + (uint32_t)(s * 1024 + 512 + chunk_pos(row, c)) * 16,
                       B + (size_t)bcl * K3 + k0 + c * 8, brow < N ? 16 : 0);
        }
    };

    load_tile(0, 0); asm volatile("cp.async.commit_group;");
    load_tile(1, 1); asm volatile("cp.async.commit_group;");

    for (int kt = 0; kt < K3T; kt++) {
        asm volatile("cp.async.wait_group 1;");
        __syncthreads();

        if (kt + 2 < K3T) load_tile(kt + 2, (kt + 2) % 3);
        asm volatile("cp.async.commit_group;");

        const int s = kt % 3;
        const uint32_t abase = sbase + (uint32_t)(s * 1024) * 16;
        const uint32_t bbase = sbase + (uint32_t)(s * 1024 + 512) * 16;

#pragma unroll
        for (int ks = 0; ks < 2; ks++) {
            const int c = ks * 2 + lc_hi;
            uint32_t af[2][4];
#pragma unroll
            for (int mi = 0; mi < 2; mi++) {
                const int r = wm + mi * 16 + lrow;
                ldsm_x4(af[mi][0], af[mi][1], af[mi][2], af[mi][3],
                        abase + (uint32_t)chunk_pos(r, c) * 16);
            }
            uint32_t bf[8][2];
#pragma unroll
            for (int pi = 0; pi < 4; pi++) {
                const int r = wn + pi * 16 + lrow;
                uint32_t q0, q1, q2, q3;
                ldsm_x4(q0, q1, q2, q3, bbase + (uint32_t)chunk_pos(r, c) * 16);
                bf[2 * pi][0] = q0; bf[2 * pi][1] = q2;
                bf[2 * pi + 1][0] = q1; bf[2 * pi + 1][1] = q3;
            }
#pragma unroll
            for (int mi = 0; mi < 2; mi++)
#pragma unroll
                for (int ni = 0; ni < 8; ni++)
                    mma_bf16(acc[mi][ni], af[mi], bf[ni]);
        }
    }

    const int erow = (lane >> 2);
    const int ecol = (lane & 3) * 2;
#pragma unroll
    for (int mi = 0; mi < 2; mi++) {
#pragma unroll
        for (int ni = 0; ni < 8; ni++) {
            const int col = bn + wn + ni * 8 + ecol;
            if (col >= N) continue;
            const int row = bm + wm + mi * 16 + erow;
            *(float2*)(C + (size_t)row * ldc + col) =
                make_float2(acc[mi][ni][0], acc[mi][ni][1]);
            *(float2*)(C + (size_t)(row + 8) * ldc + col) =
                make_float2(acc[mi][ni][2], acc[mi][ni][3]);
        }
    }
}

// ---------------------------------------------------------------------------
// Depthwise causal conv (D_CONV=4) + bias + silu. Writes fp32 xc (scan input)
// AND bf16x3 A-mode xcb (xp-GEMM operand).
// ---------------------------------------------------------------------------
__global__ __launch_bounds__(256)
void conv_silu_kernel(const float* __restrict__ xz0,
                      const float* __restrict__ cw_f, const float* __restrict__ cb_f,
                      const float* __restrict__ cw_b, const float* __restrict__ cb_b,
                      float* __restrict__ xc0, __nv_bfloat16* __restrict__ xcb0)
{
    const int dir = blockIdx.y;
    const size_t idx = (size_t)blockIdx.x * blockDim.x + threadIdx.x;
    const int d = (int)(idx & 1023);
    const size_t row = idx >> 10;
    const int t = (int)(row & (SEQLEN - 1));
    const size_t bL = row - (size_t)t;

    const float* xz = xz0 + (size_t)dir * (size_t)MT * 2048;
    const float* cw = dir ? cw_b : cw_f;
    const float* cb = dir ? cb_b : cb_f;

    const float4 w = __ldg((const float4*)(cw + d * 4));
    float s = cb[d];
    if (dir == 0) {
        if (t - 3 >= 0) s = fmaf(w.x, xz[(bL + (size_t)(t - 3)) * 2048 + d], s);
        if (t - 2 >= 0) s = fmaf(w.y, xz[(bL + (size_t)(t - 2)) * 2048 + d], s);
        if (t - 1 >= 0) s = fmaf(w.z, xz[(bL + (size_t)(t - 1)) * 2048 + d], s);
        s = fmaf(w.w, xz[(bL + (size_t)t) * 2048 + d], s);
    } else {
        if (t + 3 < SEQLEN) s = fmaf(w.x, xz[(bL + (size_t)(t + 3)) * 2048 + d], s);
        if (t + 2 < SEQLEN) s = fmaf(w.y, xz[(bL + (size_t)(t + 2)) * 2048 + d], s);
        if (t + 1 < SEQLEN) s = fmaf(w.z, xz[(bL + (size_t)(t + 1)) * 2048 + d], s);
        s = fmaf(w.w, xz[(bL + (size_t)t) * 2048 + d], s);
    }
    const float sv = s / (1.f + __expf(-s));   // silu
    xc0[(size_t)dir * (size_t)MT * 1024 + row * 1024 + d] = sv;

    __nv_bfloat16 hi = __float2bfloat16(sv);
    __nv_bfloat16 lo = __float2bfloat16(sv - __bfloat162float(hi));
    __nv_bfloat16* ob = xcb0 + (size_t)dir * (size_t)MT * 3072 + row * 3072 + d;
    ob[0]    = hi;
    ob[1024] = lo;
    ob[2048] = hi;
}

// ---------------------------------------------------------------------------
// Selective scan + gating, cp.async 8-deep smem pipeline (MLP=8 over the
// per-step DRAM loads), power-chain exp fast path. Writes bf16x3 ygb directly.
// One CTA per (128-chan slice, batch, dir): grid (8, 8, 2), 128 threads.
// ---------------------------------------------------------------------------
#define PF 8
__global__ __launch_bounds__(128)
void scan_kernel(const float* __restrict__ dt0,
                 const float* __restrict__ dbl0,
                 const float* __restrict__ xc0,
                 const float* __restrict__ xz0,
                 const float* __restrict__ Alog_f, const float* __restrict__ Alog_b,
                 const float* __restrict__ Dp_f,   const float* __restrict__ Dp_b,
                 __nv_bfloat16* __restrict__ ygb0)
{
    __shared__ __align__(16) float sdt[PF][128];
    __shared__ __align__(16) float sxc[PF][128];
    __shared__ __align__(16) float sz [PF][128];
    __shared__ __align__(16) float sbc[PF][32];

    const int dir   = blockIdx.z;
    const int b     = blockIdx.y;
    const int dbase = blockIdx.x * 128;
    const int tid   = threadIdx.x;
    const int wid   = tid >> 5;
    const int lane  = tid & 31;
    const int d     = dbase + tid;

    const float* dt  = dt0  + (size_t)dir * (size_t)MT * 1024;
    const float* dbl = dbl0 + (size_t)dir * (size_t)MT * 64;
    const float* xc  = xc0  + (size_t)dir * (size_t)MT * 1024;
    const float* xz  = xz0  + (size_t)dir * (size_t)MT * 2048;
    __nv_bfloat16* ygb = ygb0 + (size_t)dir * (size_t)MT * 3072;
    const float* Alog = dir ? Alog_b : Alog_f;
    const float  Dv   = dir ? Dp_b[d] : Dp_f[d];

    float Aa[DSTATE];
#pragma unroll
    for (int n = 0; n < DSTATE; n++) Aa[n] = -__expf(Alog[d * DSTATE + n]);

    bool pw = true;
#pragma unroll
    for (int n = 1; n < DSTATE; n++)
        pw = pw && (fabsf(Aa[n] - Aa[0] * (float)(n + 1)) <= 1e-5f * fabsf(Aa[n]));
    pw = __all_sync(0xffffffffu, pw);

    auto stage = [&](int sp) {
        if (sp < SEQLEN) {
            const int t = dir ? (SEQLEN - 1 - sp) : sp;
            const size_t row = (size_t)b * SEQLEN + t;
            const int buf = sp & (PF - 1);
            if (wid == 0)
                cp_async16ca(smem_u32(&sdt[buf][lane * 4]),
                             dt + row * 1024 + dbase + lane * 4);
            else if (wid == 1)
                cp_async16ca(smem_u32(&sxc[buf][lane * 4]),
                             xc + row * 1024 + dbase + lane * 4);
            else if (wid == 2)
                cp_async16ca(smem_u32(&sz[buf][lane * 4]),
                             xz + row * 2048 + 1024 + dbase + lane * 4);
            else if (lane < 8)
                cp_async16ca(smem_u32(&sbc[buf][lane * 4]),
                             dbl + row * 64 + DTRANK + lane * 4);
        }
        asm volatile("cp.async.commit_group;");
    };

    float h[DSTATE];
#pragma unroll
    for (int n = 0; n < DSTATE; n++) h[n] = 0.f;

#pragma unroll
    for (int p = 0; p < PF - 1; p++) stage(p);

    for (int s = 0; s < SEQLEN; s++) {
        asm volatile("cp.async.wait_group %0;" :: "n"(PF - 2));
        __syncthreads();
        stage(s + PF - 1);   // writes buf (s-1)&7, whose compute finished pre-sync

        const int buf = s & (PF - 1);
        const float dtv = sdt[buf][tid];
        const float xv  = sxc[buf][tid];
        const float zv  = sz [buf][tid];

        float Bv[DSTATE], Cv[DSTATE];
        const float4* bp = (const float4*)&sbc[buf][0];
        *(float4*)&Bv[0]  = bp[0]; *(float4*)&Bv[4]  = bp[1];
        *(float4*)&Bv[8]  = bp[2]; *(float4*)&Bv[12] = bp[3];
        *(float4*)&Cv[0]  = bp[4]; *(float4*)&Cv[4]  = bp[5];
        *(float4*)&Cv[8]  = bp[6]; *(float4*)&Cv[12] = bp[7];

        const float u = dtv * xv;
        float y = 0.f;
        if (pw) {
            const float e1 = __expf(Aa[0] * dtv);
            float en = e1;
#pragma unroll
            for (int n = 0; n < DSTATE; n++) {
                h[n] = fmaf(en, h[n], u * Bv[n]);
                y = fmaf(h[n], Cv[n], y);
                en *= e1;
            }
        } else {
#pragma unroll
            for (int n = 0; n < DSTATE; n++) {
                const float en = __expf(Aa[n] * dtv);
                h[n] = fmaf(en, h[n], u * Bv[n]);
                y = fmaf(h[n], Cv[n], y);
            }
        }
        const float yo = y + xv * Dv;
        const float sg = zv / (1.f + __expf(-zv));
        const float yv = yo * sg;

        const int t = dir ? (SEQLEN - 1 - s) : s;
        const size_t row = (size_t)b * SEQLEN + t;
        __nv_bfloat16 hi = __float2bfloat16(yv);
        __nv_bfloat16 lo = __float2bfloat16(yv - __bfloat162float(hi));
        __nv_bfloat16* ob = ygb + row * 3072 + d;
        ob[0]    = hi;
        ob[1024] = lo;
        ob[2048] = hi;
    }
}

// ---------------------------------------------------------------------------
// Host launch sequence (graph-capturable: kernel launches only)
// ---------------------------------------------------------------------------
static float* symaddrf(const void* sym) {
    void* p = nullptr; cudaGetSymbolAddress(&p, sym); return (float*)p;
}
static __nv_bfloat16* symaddrb(const void* sym) {
    void* p = nullptr; cudaGetSymbolAddress(&p, sym); return (__nv_bfloat16*)p;
}

static inline void cvt3(const float* in, __nv_bfloat16* out, int R, int K,
                        int in_ld, int modeB) {
    const int total4 = R * (K / 4);
    cvt3_kernel<<<(total4 + 255) / 256, 256>>>(in, out, K, in_ld, total4, modeB);
}

extern "C" void kernel_launch(void* const* d_in, const int* in_sizes, int n_in,
                              void* d_out, int out_size)
{
    const float* x        = (const float*)d_in[0];
    const float* f_in_w   = (const float*)d_in[1];
    const float* f_conv_w = (const float*)d_in[2];
    const float* f_conv_b = (const float*)d_in[3];
    const float* f_xp_w   = (const float*)d_in[4];
    const float* f_dt_w   = (const float*)d_in[5];
    const float* f_dt_b   = (const float*)d_in[6];
    const float* f_A_log  = (const float*)d_in[7];
    const float* f_Dp     = (const float*)d_in[8];
    const float* f_out_w  = (const float*)d_in[9];
    const float* b_in_w   = (const float*)d_in[10];
    const float* b_conv_w = (const float*)d_in[11];
    const float* b_conv_b = (const float*)d_in[12];
    const float* b_xp_w   = (const float*)d_in[13];
    const float* b_dt_w   = (const float*)d_in[14];
    const float* b_dt_b   = (const float*)d_in[15];
    const float* b_A_log  = (const float*)d_in[16];
    const float* b_Dp     = (const float*)d_in[17];
    const float* b_out_w  = (const float*)d_in[18];
    const float* lin_w    = (const float*)d_in[19];
    const float* lin_b    = (const float*)d_in[20];
    float* out = (float*)d_out;

    float* xz   = symaddrf(g_xz);
    float* xc   = symaddrf(g_xc);
    float* dbl  = symaddrf(g_dbl);
    float* dtb  = symaddrf(g_dt);

    __nv_bfloat16* xb    = symaddrb(g_xb);
    __nv_bfloat16* xcb   = symaddrb(g_xcb);
    __nv_bfloat16* dblb  = symaddrb(g_dblb);
    __nv_bfloat16* ygb   = symaddrb(g_ygb);
    __nv_bfloat16* ycatb = symaddrb(g_ycatb);
    __nv_bfloat16* wb    = symaddrb(g_wb);

    const size_t XZ   = (size_t)MT * 2048;
    const size_t XC   = (size_t)MT * 1024;
    const size_t DBL  = (size_t)MT * 64;
    const size_t XCB  = (size_t)MT * 3072;
    const size_t DBLB = (size_t)MT * 96;

    // 0) operand conversions (weights B-mode, x A-mode)
    cvt3(x,       xb,               MT,   512,  512,  0);
    cvt3(f_in_w,  wb + OFF_INW_F,   2048, 512,  512,  1);
    cvt3(b_in_w,  wb + OFF_INW_B,   2048, 512,  512,  1);
    cvt3(f_xp_w,  wb + OFF_XPW_F,   64,   1024, 1024, 1);
    cvt3(b_xp_w,  wb + OFF_XPW_B,   64,   1024, 1024, 1);
    cvt3(f_dt_w,  wb + OFF_DTW_F,   1024, 32,   32,   1);
    cvt3(b_dt_w,  wb + OFF_DTW_B,   1024, 32,   32,   1);
    cvt3(f_out_w, wb + OFF_OUTW_F,  512,  1024, 1024, 1);
    cvt3(b_out_w, wb + OFF_OUTW_B,  512,  1024, 1024, 1);
    cvt3(lin_w,   wb + OFF_LINW,    512,  1024, 1024, 1);

    // 1) xz = x @ in_w^T  (M=16384, N=2048, K3=1536), both dirs in grid.z
    bgemm_w<0, 0><<<dim3(16, 128, 2), 128>>>(
        xb, wb + OFF_INW_F, xz, nullptr, nullptr,
        2048, 1536, 2048, 0, (size_t)(OFF_INW_B - OFF_INW_F), XZ, 0, 0, 0);

    // 2) depthwise conv + silu -> xc (fp32) + xcb (bf16x3), both dirs
    conv_silu_kernel<<<dim3((unsigned)(XC / 256), 2), 256>>>(
        xz, f_conv_w, f_conv_b, b_conv_w, b_conv_b, xc, xcb);

    // 3) dbl = xc @ xp_w^T  (N=64, K3=3072), both dirs
    bgemm_nt<<<dim3(1, 128, 2), 256>>>(
        xcb, wb + OFF_XPW_F, dbl, MT, 64, 3072, 64,
        XCB, (size_t)(OFF_XPW_B - OFF_XPW_F), DBL);

    // 4) dt = softplus(dbl[:, :32] @ dt_w^T + dt_b)  (N=1024, K3=96), both dirs
    cvt3(dbl,       dblb,        MT, 32, 64, 0);
    cvt3(dbl + DBL, dblb + DBLB, MT, 32, 64, 0);
    bgemm_w<1, 0><<<dim3(8, 128, 2), 128>>>(
        dblb, wb + OFF_DTW_F, dtb, f_dt_b, b_dt_b,
        1024, 96, 1024, DBLB, (size_t)(OFF_DTW_B - OFF_DTW_F), XC, 0, 0, 0);

    // 5) selective scan + gating -> ygb (bf16x3), both dirs
    scan_kernel<<<dim3(8, BATCH, 2), 128>>>(
        dtb, dbl, xc, xz, f_A_log, b_A_log, f_Dp, b_Dp, ygb);

    // 6) y_dir = yg @ out_w^T -> ycatb[:, dir*512:+512] (bf16x3, KO=1024)
    bgemm_w<0, 1><<<dim3(4, 128, 2), 128>>>(
        ygb, wb + OFF_OUTW_F, ycatb, nullptr, nullptr,
        512, 3072, 0, XCB, (size_t)(OFF_OUTW_B - OFF_OUTW_F), 0, 0, 512, 1024);

    // 7) out = ycat @ lin_w^T + lin_b  (N=512, K3=3072)
    bgemm_w<2, 0><<<dim3(4, 128, 1), 128>>>(
        ycatb, wb + OFF_LINW, out, lin_b, lin_b,
        512, 3072, 512, 0, 0, 0, 0, 0, 0);
}

// round 15
// speedup vs baseline: 3.2881x; 1.2740x over previous
#include <cuda_runtime.h>
#include <cuda_fp16.h>
#include <cuda_bf16.h>
#include <cstdint>
#include <math.h>

// ---------------------------------------------------------------------------
// BiMamba: bidirectional Mamba block.
// GEMMs: mma.sync fp16 with activation hi/lo 2-way K-split (weights fp16-
// quantized once => only error source). out-proj+lin algebraically fused into
// one GEMM via precomputed M = lin_slice @ out_w. Scan cp.async-pipelined.
// B=8, L=2048, D_MODEL=512, D_INNER=1024, D_STATE=16, DT_RANK=32, D_CONV=4
// ---------------------------------------------------------------------------

#define BATCH   8
#define SEQLEN  2048
#define DSTATE  16
#define DTRANK  32
#define MT      (BATCH * SEQLEN)          // 16384 token rows

// --------------------------- fp32 scratch ----------------------------------
__device__ float g_xz  [2 * (size_t)MT * 2048];   // xi | z   (per dir)
__device__ float g_xc  [2 * (size_t)MT * 1024];   // conv+silu output (scan input)
__device__ float g_dbl [2 * (size_t)MT * 64];     // dt_lowrank | B | C
__device__ float g_dt  [2 * (size_t)MT * 1024];   // softplus dt

// --------------------------- fp16 2-split operands --------------------------
// A-mode along K: [hi | lo] (x reconstructed exactly); B-mode: [Hi | Hi]
__device__ __half g_xb   [(size_t)MT * 1024];     // x        (A, K2=1024)
__device__ __half g_xcb  [2 * (size_t)MT * 2048]; // conv out (A, K2=2048)
__device__ __half g_dblb [2 * (size_t)MT * 64];   // dt-lowrank (A, K2=64)
__device__ __half g_ygc  [(size_t)MT * 4096];     // [ygf hi|lo | ygb hi|lo]
__device__ __half g_w2   [4587520];               // in/xp/dt weights (B-mode)
__device__ __half g_mcat [512 * 4096];            // fused out+lin weights (B-mode)

// offsets in g_w2 (halfs)
#define OFF_INW_F   0u
#define OFF_INW_B   2097152u
#define OFF_XPW_F   4194304u
#define OFF_XPW_B   4325376u
#define OFF_DTW_F   4456448u
#define OFF_DTW_B   4521984u

// --------------------------- helpers ---------------------------------------
__device__ __forceinline__ float softplus_f(float v) {
    return v > 20.f ? v : log1pf(__expf(v));
}
__device__ __forceinline__ unsigned short h16(__half h) {
    unsigned short s; memcpy(&s, &h, 2); return s;
}
__device__ __forceinline__ uint32_t smem_u32(const void* p) {
    return (uint32_t)__cvta_generic_to_shared(p);
}
__device__ __forceinline__ void cp_async16(uint32_t s, const void* g, int sz) {
    asm volatile("cp.async.cg.shared.global [%0], [%1], 16, %2;\n"
                 :: "r"(s), "l"(g), "r"(sz));
}
__device__ __forceinline__ void cp_async16ca(uint32_t s, const void* g) {
    asm volatile("cp.async.ca.shared.global [%0], [%1], 16;\n"
                 :: "r"(s), "l"(g));
}
__device__ __forceinline__ void ldsm_x4(uint32_t& r0, uint32_t& r1,
                                        uint32_t& r2, uint32_t& r3, uint32_t addr) {
    asm volatile("ldmatrix.sync.aligned.m8n8.x4.shared.b16 {%0,%1,%2,%3}, [%4];"
                 : "=r"(r0), "=r"(r1), "=r"(r2), "=r"(r3) : "r"(addr));
}
__device__ __forceinline__ void mma_f16(float* c, const uint32_t* a, const uint32_t* b) {
    asm volatile("mma.sync.aligned.m16n8k16.row.col.f32.f16.f16.f32 "
                 "{%0,%1,%2,%3},{%4,%5,%6,%7},{%8,%9},{%0,%1,%2,%3};"
                 : "+f"(c[0]), "+f"(c[1]), "+f"(c[2]), "+f"(c[3])
                 : "r"(a[0]), "r"(a[1]), "r"(a[2]), "r"(a[3]),
                   "r"(b[0]), "r"(b[1]));
}
// swizzled chunk position (16B units) within a 128x32 fp16 tile
__device__ __forceinline__ int chunk_pos(int row, int c) {
    return row * 4 + (c ^ ((row >> 1) & 3));
}

// ---------------------------------------------------------------------------
// cvt2: fp32 [R,K] (row stride in_ld) -> fp16 [R,2K].
// modeB=0 (A operand): [hi | lo] ; modeB=1 (B operand): [Hi | Hi]
// ---------------------------------------------------------------------------
__global__ __launch_bounds__(256)
void cvt2_kernel(const float* __restrict__ in, __half* __restrict__ out,
                 int K, int in_ld, int total4, int modeB)
{
    const int idx = blockIdx.x * blockDim.x + threadIdx.x;
    if (idx >= total4) return;
    const int kq = K >> 2;
    const int r  = idx / kq;
    const int k  = (idx - r * kq) * 4;

    const float4 v = *(const float4*)(in + (size_t)r * in_ld + k);
    float vv[4] = {v.x, v.y, v.z, v.w};
    unsigned short hb[4], lb[4];
#pragma unroll
    for (int j = 0; j < 4; j++) {
        __half h = __float2half_rn(vv[j]);
        __half l = __float2half_rn(vv[j] - __half2float(h));
        hb[j] = h16(h); lb[j] = h16(l);
    }
    uint2 H, L;
    H.x = (uint32_t)hb[0] | ((uint32_t)hb[1] << 16);
    H.y = (uint32_t)hb[2] | ((uint32_t)hb[3] << 16);
    L.x = (uint32_t)lb[0] | ((uint32_t)lb[1] << 16);
    L.y = (uint32_t)lb[2] | ((uint32_t)lb[3] << 16);

    __half* ob = out + (size_t)r * (2 * K) + k;
    *(uint2*)(ob)     = H;
    *(uint2*)(ob + K) = modeB ? H : L;
}

// ---------------------------------------------------------------------------
// fuse_w: Mcat[o, dir*2048 + {d, 1024+d}] = fp16( sum_i lin_w[o, dir*512+i] *
//         out_w_dir[i, d] ), o<512, d<1024.  8 o-rows per block via smem.
// ---------------------------------------------------------------------------
__global__ __launch_bounds__(128)
void fuse_w_kernel(const float* __restrict__ lin_w,
                   const float* __restrict__ ow_f, const float* __restrict__ ow_b,
                   __half* __restrict__ mcat)
{
    __shared__ float sl[8][512];
    const int dir = blockIdx.z;
    const float* ow = dir ? ow_b : ow_f;
    const int off = dir * 512;
    const int tid = threadIdx.x;
    const int d   = blockIdx.x * 128 + tid;
    const int og  = blockIdx.y * 8;

    for (int idx = tid; idx < 8 * 128; idx += 128) {
        const int j = idx >> 7;
        const int i = (idx & 127) * 4;
        *(float4*)&sl[j][i] = *(const float4*)(lin_w + (size_t)(og + j) * 1024 + off + i);
    }
    __syncthreads();

    float acc[8];
#pragma unroll
    for (int j = 0; j < 8; j++) acc[j] = 0.f;

    for (int i = 0; i < 512; i++) {
        const float wv = __ldg(ow + (size_t)i * 1024 + d);
#pragma unroll
        for (int j = 0; j < 8; j++) acc[j] = fmaf(sl[j][i], wv, acc[j]);
    }
#pragma unroll
    for (int j = 0; j < 8; j++) {
        const __half h = __float2half_rn(acc[j]);
        __half* base = mcat + (size_t)(og + j) * 4096 + dir * 2048 + d;
        base[0]    = h;
        base[1024] = h;
    }
}

// ===========================================================================
// bgemm_w: mma.sync fp16 NT GEMM, 128x128 CTA tile, 4 warps, 64x64 warp tile.
// A:[M,K2], B:[N,K2] fp16 row-major. grid.z = dir (pointer strides sA/sB/sC).
// EPI: 0 none, 1 softplus(v+bias[n]), 2 v+bias[n].  C fp32.
// Requires M%128==0, N%128==0, K2%32==0, K2>=64.
// ===========================================================================
template <int EPI>
__global__ __launch_bounds__(128, 2)
void bgemm_w(const __half* __restrict__ A0,
             const __half* __restrict__ B0,
             float* __restrict__ C0,
             const float* __restrict__ biasf, const float* __restrict__ biasb,
             int N, int K2, int ldc,
             size_t sA, size_t sB, size_t sC)
{
    __shared__ __align__(16) __half smem[3 * 2 * 128 * 32];  // 48KB
    const uint32_t sbase = smem_u32(smem);

    const int z = blockIdx.z;
    const __half* A = A0 + (size_t)z * sA;
    const __half* B = B0 + (size_t)z * sB;
    const float* bias = z ? biasb : biasf;

    const int tid  = threadIdx.x;
    const int warp = tid >> 5;
    const int lane = tid & 31;
    const int bm   = blockIdx.y * 128;
    const int bn   = blockIdx.x * 128;
    const int wm   = (warp & 1) * 64;
    const int wn   = (warp >> 1) * 64;
    const int lrow = lane & 15;
    const int lc_hi = lane >> 4;

    float acc[4][8][4];
#pragma unroll
    for (int mi = 0; mi < 4; mi++)
#pragma unroll
        for (int ni = 0; ni < 8; ni++)
#pragma unroll
            for (int q = 0; q < 4; q++) acc[mi][ni][q] = 0.f;

    const int K2T = K2 >> 5;

    auto load_tile = [&](int kt, int s) {
        const int k0 = kt * 32;
#pragma unroll
        for (int i = 0; i < 4; i++) {
            const int idx = tid + i * 128;
            const int row = idx >> 2;
            const int c   = idx & 3;
            cp_async16(sbase + (uint32_t)(s * 1024 + chunk_pos(row, c)) * 16,
                       A + (size_t)(bm + row) * K2 + k0 + c * 8, 16);
            cp_async16(sbase + (uint32_t)(s * 1024 + 512 + chunk_pos(row, c)) * 16,
                       B + (size_t)(bn + row) * K2 + k0 + c * 8, 16);
        }
    };

    load_tile(0, 0); asm volatile("cp.async.commit_group;");
    load_tile(1, 1); asm volatile("cp.async.commit_group;");

    for (int kt = 0; kt < K2T; kt++) {
        asm volatile("cp.async.wait_group 1;");
        __syncthreads();

        if (kt + 2 < K2T) load_tile(kt + 2, (kt + 2) % 3);
        asm volatile("cp.async.commit_group;");

        const int s = kt % 3;
        const uint32_t abase = sbase + (uint32_t)(s * 1024) * 16;
        const uint32_t bbase = sbase + (uint32_t)(s * 1024 + 512) * 16;

#pragma unroll
        for (int ks = 0; ks < 2; ks++) {
            const int c = ks * 2 + lc_hi;
            uint32_t af[4][4];
#pragma unroll
            for (int mi = 0; mi < 4; mi++) {
                const int r = wm + mi * 16 + lrow;
                ldsm_x4(af[mi][0], af[mi][1], af[mi][2], af[mi][3],
                        abase + (uint32_t)chunk_pos(r, c) * 16);
            }
            uint32_t bf[8][2];
#pragma unroll
            for (int pi = 0; pi < 4; pi++) {
                const int r = wn + pi * 16 + lrow;
                uint32_t q0, q1, q2, q3;
                ldsm_x4(q0, q1, q2, q3, bbase + (uint32_t)chunk_pos(r, c) * 16);
                bf[2 * pi][0] = q0; bf[2 * pi][1] = q2;
                bf[2 * pi + 1][0] = q1; bf[2 * pi + 1][1] = q3;
            }
#pragma unroll
            for (int mi = 0; mi < 4; mi++)
#pragma unroll
                for (int ni = 0; ni < 8; ni++)
                    mma_f16(acc[mi][ni], af[mi], bf[ni]);
        }
    }

    const int erow = (lane >> 2);
    const int ecol = (lane & 3) * 2;
    float* C = C0 + (size_t)z * sC;
#pragma unroll
    for (int mi = 0; mi < 4; mi++) {
#pragma unroll
        for (int ni = 0; ni < 8; ni++) {
            const int col = bn + wn + ni * 8 + ecol;
            const int row = bm + wm + mi * 16 + erow;
            float v0 = acc[mi][ni][0], v1 = acc[mi][ni][1];
            float v2 = acc[mi][ni][2], v3 = acc[mi][ni][3];
            if (EPI == 1) {
                const float b0 = bias[col], b1 = bias[col + 1];
                v0 = softplus_f(v0 + b0); v1 = softplus_f(v1 + b1);
                v2 = softplus_f(v2 + b0); v3 = softplus_f(v3 + b1);
            }
            if (EPI == 2) {
                const float b0 = bias[col], b1 = bias[col + 1];
                v0 += b0; v1 += b1; v2 += b0; v3 += b1;
            }
            *(float2*)(C + (size_t)row * ldc + col)       = make_float2(v0, v1);
            *(float2*)(C + (size_t)(row + 8) * ldc + col) = make_float2(v2, v3);
        }
    }
}

// ---------------------------------------------------------------------------
// bgemm_nt: 8-warp fp16 kernel for the skinny xp GEMM (N=64, col clamps).
// grid.z = dir.
// ---------------------------------------------------------------------------
__global__ __launch_bounds__(256, 2)
void bgemm_nt(const __half* __restrict__ A0,
              const __half* __restrict__ B0,
              float* __restrict__ C0,
              int M, int N, int K2, int ldc,
              size_t sA, size_t sB, size_t sC)
{
    __shared__ __align__(16) __half smem[3 * 2 * 128 * 32];
    const uint32_t sbase = smem_u32(smem);

    const int z = blockIdx.z;
    const __half* A = A0 + (size_t)z * sA;
    const __half* B = B0 + (size_t)z * sB;
    float* C = C0 + (size_t)z * sC;

    const int tid  = threadIdx.x;
    const int bm   = blockIdx.y * 128;
    const int bn   = blockIdx.x * 128;
    const int warp = tid >> 5;
    const int lane = tid & 31;
    const int wm   = (warp >> 1) * 32;
    const int wn   = (warp & 1) * 64;

    const int l_row0 = tid >> 1;
    const int l_c0   = (tid & 1) * 2;

    const int lrow = lane & 15;
    const int lc_hi = lane >> 4;

    float acc[2][8][4];
#pragma unroll
    for (int mi = 0; mi < 2; mi++)
#pragma unroll
        for (int ni = 0; ni < 8; ni++)
#pragma unroll
            for (int q = 0; q < 4; q++) acc[mi][ni][q] = 0.f;

    const int K2T = K2 >> 5;

    auto load_tile = [&](int kt, int s) {
        const int k0 = kt * 32;
#pragma unroll
        for (int cc = 0; cc < 2; cc++) {
            const int row = l_row0, c = l_c0 + cc;
            cp_async16(sbase + (uint32_t)(s * 1024 + chunk_pos(row, c)) * 16,
                       A + (size_t)(bm + row) * K2 + k0 + c * 8, 16);
            const int brow = bn + row;
            const int bcl  = brow < N ? brow : (N - 1);
            cp_async16(sbase + (uint32_t)(s * 1024 + 512 + chunk_pos(row, c)) * 16,
                       B + (size_t)bcl * K2 + k0 + c * 8, brow < N ? 16 : 0);
        }
    };

    load_tile(0, 0); asm volatile("cp.async.commit_group;");
    load_tile(1, 1); asm volatile("cp.async.commit_group;");

    for (int kt = 0; kt < K2T; kt++) {
        asm volatile("cp.async.wait_group 1;");
        __syncthreads();

        if (kt + 2 < K2T) load_tile(kt + 2, (kt + 2) % 3);
        asm volatile("cp.async.commit_group;");

        const int s = kt % 3;
        const uint32_t abase = sbase + (uint32_t)(s * 1024) * 16;
        const uint32_t bbase = sbase + (uint32_t)(s * 1024 + 512) * 16;

#pragma unroll
        for (int ks = 0; ks < 2; ks++) {
            const int c = ks * 2 + lc_hi;
            uint32_t af[2][4];
#pragma unroll
            for (int mi = 0; mi < 2; mi++) {
                const int r = wm + mi * 16 + lrow;
                ldsm_x4(af[mi][0], af[mi][1], af[mi][2], af[mi][3],
                        abase + (uint32_t)chunk_pos(r, c) * 16);
            }
            uint32_t bf[8][2];
#pragma unroll
            for (int pi = 0; pi < 4; pi++) {
                const int r = wn + pi * 16 + lrow;
                uint32_t q0, q1, q2, q3;
                ldsm_x4(q0, q1, q2, q3, bbase + (uint32_t)chunk_pos(r, c) * 16);
                bf[2 * pi][0] = q0; bf[2 * pi][1] = q2;
                bf[2 * pi + 1][0] = q1; bf[2 * pi + 1][1] = q3;
            }
#pragma unroll
            for (int mi = 0; mi < 2; mi++)
#pragma unroll
                for (int ni = 0; ni < 8; ni++)
                    mma_f16(acc[mi][ni], af[mi], bf[ni]);
        }
    }

    const int erow = (lane >> 2);
    const int ecol = (lane & 3) * 2;
#pragma unroll
    for (int mi = 0; mi < 2; mi++) {
#pragma unroll
        for (int ni = 0; ni < 8; ni++) {
            const int col = bn + wn + ni * 8 + ecol;
            if (col >= N) continue;
            const int row = bm + wm + mi * 16 + erow;
            *(float2*)(C + (size_t)row * ldc + col) =
                make_float2(acc[mi][ni][0], acc[mi][ni][1]);
            *(float2*)(C + (size_t)(row + 8) * ldc + col) =
                make_float2(acc[mi][ni][2], acc[mi][ni][3]);
        }
    }
}

// ---------------------------------------------------------------------------
// Depthwise causal conv (D_CONV=4) + bias + silu. Writes fp32 xc (scan input)
// and fp16 [hi|lo] xcb (xp-GEMM A operand).
// ---------------------------------------------------------------------------
__global__ __launch_bounds__(256)
void conv_silu_kernel(const float* __restrict__ xz0,
                      const float* __restrict__ cw_f, const float* __restrict__ cb_f,
                      const float* __restrict__ cw_b, const float* __restrict__ cb_b,
                      float* __restrict__ xc0, __half* __restrict__ xcb0)
{
    const int dir = blockIdx.y;
    const size_t idx = (size_t)blockIdx.x * blockDim.x + threadIdx.x;
    const int d = (int)(idx & 1023);
    const size_t row = idx >> 10;
    const int t = (int)(row & (SEQLEN - 1));
    const size_t bL = row - (size_t)t;

    const float* xz = xz0 + (size_t)dir * (size_t)MT * 2048;
    const float* cw = dir ? cw_b : cw_f;
    const float* cb = dir ? cb_b : cb_f;

    const float4 w = __ldg((const float4*)(cw + d * 4));
    float s = cb[d];
    if (dir == 0) {
        if (t - 3 >= 0) s = fmaf(w.x, xz[(bL + (size_t)(t - 3)) * 2048 + d], s);
        if (t - 2 >= 0) s = fmaf(w.y, xz[(bL + (size_t)(t - 2)) * 2048 + d], s);
        if (t - 1 >= 0) s = fmaf(w.z, xz[(bL + (size_t)(t - 1)) * 2048 + d], s);
        s = fmaf(w.w, xz[(bL + (size_t)t) * 2048 + d], s);
    } else {
        if (t + 3 < SEQLEN) s = fmaf(w.x, xz[(bL + (size_t)(t + 3)) * 2048 + d], s);
        if (t + 2 < SEQLEN) s = fmaf(w.y, xz[(bL + (size_t)(t + 2)) * 2048 + d], s);
        if (t + 1 < SEQLEN) s = fmaf(w.z, xz[(bL + (size_t)(t + 1)) * 2048 + d], s);
        s = fmaf(w.w, xz[(bL + (size_t)t) * 2048 + d], s);
    }
    const float sv = s / (1.f + __expf(-s));   // silu
    xc0[(size_t)dir * (size_t)MT * 1024 + row * 1024 + d] = sv;

    const __half hi = __float2half_rn(sv);
    const __half lo = __float2half_rn(sv - __half2float(hi));
    __half* ob = xcb0 + (size_t)dir * (size_t)MT * 2048 + row * 2048 + d;
    ob[0]    = hi;
    ob[1024] = lo;
}

// ---------------------------------------------------------------------------
// Selective scan + gating, cp.async 8-deep pipeline, power-chain exp fast
// path. Writes fp16 [hi|lo] directly into the fused-output A operand ygc:
// row layout [ygf_hi(1024) | ygf_lo(1024) | ygb_hi(1024) | ygb_lo(1024)].
// ---------------------------------------------------------------------------
#define PF 8
__global__ __launch_bounds__(128)
void scan_kernel(const float* __restrict__ dt0,
                 const float* __restrict__ dbl0,
                 const float* __restrict__ xc0,
                 const float* __restrict__ xz0,
                 const float* __restrict__ Alog_f, const float* __restrict__ Alog_b,
                 const float* __restrict__ Dp_f,   const float* __restrict__ Dp_b,
                 __half* __restrict__ ygc)
{
    __shared__ __align__(16) float sdt[PF][128];
    __shared__ __align__(16) float sxc[PF][128];
    __shared__ __align__(16) float sz [PF][128];
    __shared__ __align__(16) float sbc[PF][32];

    const int dir   = blockIdx.z;
    const int b     = blockIdx.y;
    const int dbase = blockIdx.x * 128;
    const int tid   = threadIdx.x;
    const int wid   = tid >> 5;
    const int lane  = tid & 31;
    const int d     = dbase + tid;

    const float* dt  = dt0  + (size_t)dir * (size_t)MT * 1024;
    const float* dbl = dbl0 + (size_t)dir * (size_t)MT * 64;
    const float* xc  = xc0  + (size_t)dir * (size_t)MT * 1024;
    const float* xz  = xz0  + (size_t)dir * (size_t)MT * 2048;
    const float* Alog = dir ? Alog_b : Alog_f;
    const float  Dv   = dir ? Dp_b[d] : Dp_f[d];

    float Aa[DSTATE];
#pragma unroll
    for (int n = 0; n < DSTATE; n++) Aa[n] = -__expf(Alog[d * DSTATE + n]);

    bool pw = true;
#pragma unroll
    for (int n = 1; n < DSTATE; n++)
        pw = pw && (fabsf(Aa[n] - Aa[0] * (float)(n + 1)) <= 1e-5f * fabsf(Aa[n]));
    pw = __all_sync(0xffffffffu, pw);

    auto stage = [&](int sp) {
        if (sp < SEQLEN) {
            const int t = dir ? (SEQLEN - 1 - sp) : sp;
            const size_t row = (size_t)b * SEQLEN + t;
            const int buf = sp & (PF - 1);
            if (wid == 0)
                cp_async16ca(smem_u32(&sdt[buf][lane * 4]),
                             dt + row * 1024 + dbase + lane * 4);
            else if (wid == 1)
                cp_async16ca(smem_u32(&sxc[buf][lane * 4]),
                             xc + row * 1024 + dbase + lane * 4);
            else if (wid == 2)
                cp_async16ca(smem_u32(&sz[buf][lane * 4]),
                             xz + row * 2048 + 1024 + dbase + lane * 4);
            else if (lane < 8)
                cp_async16ca(smem_u32(&sbc[buf][lane * 4]),
                             dbl + row * 64 + DTRANK + lane * 4);
        }
        asm volatile("cp.async.commit_group;");
    };

    float h[DSTATE];
#pragma unroll
    for (int n = 0; n < DSTATE; n++) h[n] = 0.f;

#pragma unroll
    for (int p = 0; p < PF - 1; p++) stage(p);

    for (int s = 0; s < SEQLEN; s++) {
        asm volatile("cp.async.wait_group %0;" :: "n"(PF - 2));
        __syncthreads();
        stage(s + PF - 1);

        const int buf = s & (PF - 1);
        const float dtv = sdt[buf][tid];
        const float xv  = sxc[buf][tid];
        const float zv  = sz [buf][tid];

        float Bv[DSTATE], Cv[DSTATE];
        const float4* bp = (const float4*)&sbc[buf][0];
        *(float4*)&Bv[0]  = bp[0]; *(float4*)&Bv[4]  = bp[1];
        *(float4*)&Bv[8]  = bp[2]; *(float4*)&Bv[12] = bp[3];
        *(float4*)&Cv[0]  = bp[4]; *(float4*)&Cv[4]  = bp[5];
        *(float4*)&Cv[8]  = bp[6]; *(float4*)&Cv[12] = bp[7];

        const float u = dtv * xv;
        float y = 0.f;
        if (pw) {
            const float e1 = __expf(Aa[0] * dtv);
            float en = e1;
#pragma unroll
            for (int n = 0; n < DSTATE; n++) {
                h[n] = fmaf(en, h[n], u * Bv[n]);
                y = fmaf(h[n], Cv[n], y);
                en *= e1;
            }
        } else {
#pragma unroll
            for (int n = 0; n < DSTATE; n++) {
                const float en = __expf(Aa[n] * dtv);
                h[n] = fmaf(en, h[n], u * Bv[n]);
                y = fmaf(h[n], Cv[n], y);
            }
        }
        const float yo = y + xv * Dv;
        const float sg = zv / (1.f + __expf(-zv));
        const float yv = yo * sg;

        const int t = dir ? (SEQLEN - 1 - s) : s;
        const size_t row = (size_t)b * SEQLEN + t;
        const __half hi = __float2half_rn(yv);
        const __half lo = __float2half_rn(yv - __half2float(hi));
        __half* ob = ygc + row * 4096 + dir * 2048 + d;
        ob[0]    = hi;
        ob[1024] = lo;
    }
}

// ---------------------------------------------------------------------------
// Host launch sequence (graph-capturable: kernel launches only)
// ---------------------------------------------------------------------------
static float* symaddrf(const void* sym) {
    void* p = nullptr; cudaGetSymbolAddress(&p, sym); return (float*)p;
}
static __half* symaddrh(const void* sym) {
    void* p = nullptr; cudaGetSymbolAddress(&p, sym); return (__half*)p;
}

static inline void cvt2(const float* in, __half* out, int R, int K,
                        int in_ld, int modeB) {
    const int total4 = R * (K / 4);
    cvt2_kernel<<<(total4 + 255) / 256, 256>>>(in, out, K, in_ld, total4, modeB);
}

extern "C" void kernel_launch(void* const* d_in, const int* in_sizes, int n_in,
                              void* d_out, int out_size)
{
    const float* x        = (const float*)d_in[0];
    const float* f_in_w   = (const float*)d_in[1];
    const float* f_conv_w = (const float*)d_in[2];
    const float* f_conv_b = (const float*)d_in[3];
    const float* f_xp_w   = (const float*)d_in[4];
    const float* f_dt_w   = (const float*)d_in[5];
    const float* f_dt_b   = (const float*)d_in[6];
    const float* f_A_log  = (const float*)d_in[7];
    const float* f_Dp     = (const float*)d_in[8];
    const float* f_out_w  = (const float*)d_in[9];
    const float* b_in_w   = (const float*)d_in[10];
    const float* b_conv_w = (const float*)d_in[11];
    const float* b_conv_b = (const float*)d_in[12];
    const float* b_xp_w   = (const float*)d_in[13];
    const float* b_dt_w   = (const float*)d_in[14];
    const float* b_dt_b   = (const float*)d_in[15];
    const float* b_A_log  = (const float*)d_in[16];
    const float* b_Dp     = (const float*)d_in[17];
    const float* b_out_w  = (const float*)d_in[18];
    const float* lin_w    = (const float*)d_in[19];
    const float* lin_b    = (const float*)d_in[20];
    float* out = (float*)d_out;

    float* xz   = symaddrf(g_xz);
    float* xc   = symaddrf(g_xc);
    float* dbl  = symaddrf(g_dbl);
    float* dtb  = symaddrf(g_dt);

    __half* xb   = symaddrh(g_xb);
    __half* xcb  = symaddrh(g_xcb);
    __half* dblb = symaddrh(g_dblb);
    __half* ygc  = symaddrh(g_ygc);
    __half* w2   = symaddrh(g_w2);
    __half* mcat = symaddrh(g_mcat);

    const size_t XZ   = (size_t)MT * 2048;
    const size_t XC   = (size_t)MT * 1024;
    const size_t DBL  = (size_t)MT * 64;
    const size_t XCB  = (size_t)MT * 2048;

    // 0) weight prep: fp16 B-mode conversions + fused out+lin weights
    cvt2(f_in_w,  w2 + OFF_INW_F, 2048, 512,  512,  1);
    cvt2(b_in_w,  w2 + OFF_INW_B, 2048, 512,  512,  1);
    cvt2(f_xp_w,  w2 + OFF_XPW_F, 64,   1024, 1024, 1);
    cvt2(b_xp_w,  w2 + OFF_XPW_B, 64,   1024, 1024, 1);
    cvt2(f_dt_w,  w2 + OFF_DTW_F, 1024, 32,   32,   1);
    cvt2(b_dt_w,  w2 + OFF_DTW_B, 1024, 32,   32,   1);
    fuse_w_kernel<<<dim3(8, 64, 2), 128>>>(lin_w, f_out_w, b_out_w, mcat);

    // activation A-mode conversion for x
    cvt2(x, xb, MT, 512, 512, 0);

    // 1) xz = x @ in_w^T  (M=16384, N=2048, K2=1024), both dirs in grid.z
    bgemm_w<0><<<dim3(16, 128, 2), 128>>>(
        xb, w2 + OFF_INW_F, xz, nullptr, nullptr,
        2048, 1024, 2048, 0, (size_t)(OFF_INW_B - OFF_INW_F), XZ);

    // 2) depthwise conv + silu -> xc (fp32) + xcb (fp16 hi|lo), both dirs
    conv_silu_kernel<<<dim3((unsigned)(XC / 256), 2), 256>>>(
        xz, f_conv_w, f_conv_b, b_conv_w, b_conv_b, xc, xcb);

    // 3) dbl = xc @ xp_w^T  (N=64, K2=2048), both dirs
    bgemm_nt<<<dim3(1, 128, 2), 256>>>(
        xcb, w2 + OFF_XPW_F, dbl, MT, 64, 2048, 64,
        XCB, (size_t)(OFF_XPW_B - OFF_XPW_F), DBL);

    // 4) dt = softplus(dbl[:, :32] @ dt_w^T + dt_b)  (N=1024, K2=64), both dirs
    cvt2(dbl,       dblb,       MT, 32, 64, 0);
    cvt2(dbl + DBL, dblb + DBL, MT, 32, 64, 0);
    bgemm_w<1><<<dim3(8, 128, 2), 128>>>(
        dblb, w2 + OFF_DTW_F, dtb, f_dt_b, b_dt_b,
        1024, 64, 1024, DBL, (size_t)(OFF_DTW_B - OFF_DTW_F), XC);

    // 5) selective scan + gating -> ygc (fused A operand), both dirs
    scan_kernel<<<dim3(8, BATCH, 2), 128>>>(
        dtb, dbl, xc, xz, f_A_log, b_A_log, f_Dp, b_Dp, ygc);

    // 6) out = ygc @ Mcat^T + lin_b  (N=512, K2=4096)  [fused out-proj + lin]
    bgemm_w<2><<<dim3(4, 128, 1), 128>>>(
        ygc, mcat, out, lin_b, lin_b,
        512, 4096, 512, 0, 0, 0);
}